// round 4
// baseline (speedup 1.0000x reference)
#include <cuda_runtime.h>
#include <cuda_bf16.h>
#include <math.h>
#include <stdint.h>

// ---------------------------------------------------------------------------
// VPGNet forward. Conv GEMMs via warp-level mma.sync bf16 (2-term split,
// fp32 accumulate). Branch phase batched across the 4 heads (blockIdx.z).
// Output: [x6 | x8a | x8b | x8c | x8d] = 1,747,200 floats
// ---------------------------------------------------------------------------

// ---- scratch (__device__ globals: no allocation allowed) ----
__device__ float g_c1[96 * 118 * 158];
__device__ float g_l1[96 * 118 * 158];
__device__ float g_u1[96 * 59 * 79];
__device__ float g_c2[256 * 59 * 79];
__device__ float g_l2[256 * 59 * 79];
__device__ float g_p2[256 * 29 * 39];
__device__ float g_c3[384 * 29 * 39];
__device__ float g_c4[384 * 29 * 39];
__device__ float g_c5[384 * 29 * 39];
__device__ float g_p5[384 * 14 * 19];
__device__ float g_x7[4 * 4096 * 300];
__device__ float g_x8[1728 * 300];
// bf16 split activation buffers [Npad][K]; max conv2: 4672*2400 = 11,212,800
// (also reused for the 4 branch x7 splits: 4 * 320*4096 = 5,242,880)
__device__ __nv_bfloat16 gB_hi[11250000];
__device__ __nv_bfloat16 gB_lo[11250000];
// dedicated split of x6 (shared by all 4 branch gemm7s)
__device__ __nv_bfloat16 gB6_hi[320 * 4096];
__device__ __nv_bfloat16 gB6_lo[320 * 4096];

// ============================ helpers ============================
__device__ __forceinline__ uint32_t smem_u32(const void* p) {
    uint32_t a;
    asm("{ .reg .u64 t; cvta.to.shared.u64 t, %1; cvt.u32.u64 %0, t; }" : "=r"(a) : "l"(p));
    return a;
}
__device__ __forceinline__ uint32_t swz64(uint32_t o) { return o ^ ((o >> 3) & 0x30); }

__device__ __forceinline__ void ldm4(uint32_t* r, uint32_t a) {
    asm volatile("ldmatrix.sync.aligned.m8n8.x4.shared.b16 {%0,%1,%2,%3}, [%4];"
                 : "=r"(r[0]), "=r"(r[1]), "=r"(r[2]), "=r"(r[3]) : "r"(a));
}
__device__ __forceinline__ void mma_bf16(float* c, const uint32_t* a, const uint32_t* b) {
    asm volatile("mma.sync.aligned.m16n8k16.row.col.f32.bf16.bf16.f32 "
                 "{%0,%1,%2,%3}, {%4,%5,%6,%7}, {%8,%9}, {%0,%1,%2,%3};"
                 : "+f"(c[0]), "+f"(c[1]), "+f"(c[2]), "+f"(c[3])
                 : "r"(a[0]), "r"(a[1]), "r"(a[2]), "r"(a[3]), "r"(b[0]), "r"(b[1]));
}
__device__ __forceinline__ void sts128(uint32_t a, uint4 v) {
    asm volatile("st.shared.v4.b32 [%0], {%1,%2,%3,%4};"
                 :: "r"(a), "r"(v.x), "r"(v.y), "r"(v.z), "r"(v.w) : "memory");
}
__device__ __forceinline__ void sts64(uint32_t a, uint32_t x, uint32_t y) {
    asm volatile("st.shared.v2.b32 [%0], {%1,%2};" :: "r"(a), "r"(x), "r"(y) : "memory");
}
__device__ __forceinline__ uint32_t packbf2(float lo, float hi) {
    uint32_t d;
    asm("cvt.rn.bf16x2.f32 %0, %1, %2;" : "=r"(d) : "f"(hi), "f"(lo));
    return d;
}

// ============================ small layers ============================
__global__ void k_conv1(const float* __restrict__ x, const float* __restrict__ w,
                        const float* __restrict__ b, float* __restrict__ out) {
    const int HO = 118, WO = 158;
    int i = blockIdx.x * blockDim.x + threadIdx.x;
    if (i >= 96 * HO * WO) return;
    int c = i / (HO * WO), r = i % (HO * WO), oh = r / WO, ow = r % WO;
    float acc = b[c];
    const float* wp = w + c * 3 * 121;
    for (int ci = 0; ci < 3; ci++) {
        const float* xc = x + ci * 480 * 640;
        const float* wc = wp + ci * 121;
        #pragma unroll
        for (int kh = 0; kh < 11; kh++) {
            const float* xp = xc + (oh * 4 + kh) * 640 + ow * 4;
            const float* wq = wc + kh * 11;
            #pragma unroll
            for (int kw = 0; kw < 11; kw++) acc = fmaf(xp[kw], wq[kw], acc);
        }
    }
    out[i] = fmaxf(acc, 0.f);
}

__global__ void k_lrn(const float* __restrict__ in, float* __restrict__ out,
                      int C, int HW, float kconst, float a) {
    int i = blockIdx.x * blockDim.x + threadIdx.x;
    if (i >= C * HW) return;
    int c = i / HW, s = i % HW;
    int lo = c - 2 > 0 ? c - 2 : 0;
    int hi = c + 2 < C - 1 ? c + 2 : C - 1;
    float sum = 0.f;
    for (int j = lo; j <= hi; j++) { float v = in[j * HW + s]; sum = fmaf(v, v, sum); }
    float t = kconst + a * sum;
    float r = rsqrtf(t);                 // t^-0.5
    out[i] = in[i] * r * sqrtf(r);       // t^-0.75
}

__global__ void k_poolup(const float* __restrict__ in, float* __restrict__ out) {
    int i = blockIdx.x * blockDim.x + threadIdx.x;
    if (i >= 96 * 59 * 79) return;
    int c = i / (59 * 79), r = i % (59 * 79), oh = r / 79, ow = r % 79;
    int hi = (oh * 58) / 59, wi = (ow * 78) / 79;
    const float* p = in + (c * 118 + 2 * hi) * 158 + 2 * wi;
    float m = p[0];
    #pragma unroll
    for (int dh = 0; dh < 3; dh++)
        #pragma unroll
        for (int dw = 0; dw < 3; dw++) m = fmaxf(m, p[dh * 158 + dw]);
    out[i] = m;
}

__global__ void k_pool(const float* __restrict__ in, float* __restrict__ out,
                       int C, int Hin, int Win, int Ho, int Wo) {
    int i = blockIdx.x * blockDim.x + threadIdx.x;
    if (i >= C * Ho * Wo) return;
    int c = i / (Ho * Wo), r = i % (Ho * Wo), oh = r / Wo, ow = r % Wo;
    const float* p = in + (c * Hin + 2 * oh) * Win + 2 * ow;
    float m = p[0];
    #pragma unroll
    for (int dh = 0; dh < 3; dh++)
        #pragma unroll
        for (int dw = 0; dw < 3; dw++) m = fmaxf(m, p[dh * Win + dw]);
    out[i] = m;
}

// ---- fused im2col + transpose + bf16 split:  src (C,H,W) -> [Npad][K] hi/lo
__global__ void k_prepB(const float* __restrict__ src, __nv_bfloat16* __restrict__ hi,
                        __nv_bfloat16* __restrict__ lo, int Cc, int H, int W,
                        int ksz, int pad, int Ho, int Wo, int Kreal,
                        long total) {
    long i = blockIdx.x * (long)blockDim.x + threadIdx.x;
    if (i >= total) return;
    int kidx = (int)(i % Kreal);
    int n = (int)(i / Kreal);
    float v = 0.f;
    if (n < Ho * Wo) {
        int kw = kidx % ksz;
        int t = kidx / ksz;
        int kh = t % ksz, cc = t / ksz;
        int oh = n / Wo, ow = n % Wo;
        int ih = oh - pad + kh, iw = ow - pad + kw;
        if (ih >= 0 && ih < H && iw >= 0 && iw < W) v = src[((size_t)cc * H + ih) * W + iw];
    }
    __nv_bfloat16 h = __float2bfloat16(v);
    hi[i] = h;
    lo[i] = __float2bfloat16(v - __bfloat162float(h));
}

// ---- batched split of the four x7 tensors (1x1 conv layout, K=4096, N=300) ----
__global__ void k_prep7b(const float* __restrict__ x7, __nv_bfloat16* __restrict__ hi,
                         __nv_bfloat16* __restrict__ lo) {
    const long PER = 320L * 4096;
    long i = blockIdx.x * (long)blockDim.x + threadIdx.x;
    if (i >= 4 * PER) return;
    int z = (int)(i / PER);
    long r = i % PER;
    int n = (int)(r >> 12), k = (int)(r & 4095);
    float v = 0.f;
    if (n < 300) v = x7[(size_t)z * 1228800 + (size_t)k * 300 + n];
    __nv_bfloat16 h = __float2bfloat16(v);
    hi[i] = h;
    lo[i] = __float2bfloat16(v - __bfloat162float(h));
}

// ---- fused 4-branch pixel-shuffle tile ----
__global__ void k_tile4(const float* __restrict__ x8, float* __restrict__ out) {
    int i = blockIdx.x * blockDim.x + threadIdx.x;
    if (i >= 518400) return;
    // branch boundaries (elements): cum {76800, 115200, 422400, 518400}
    int t, start, C8, r;
    long oofs;
    if (i < 76800)       { t = 0; start = 0;      C8 = 256;  r = 8; oofs = 1228800L; }
    else if (i < 115200) { t = 1; start = 76800;  C8 = 128;  r = 8; oofs = 1305600L; }
    else if (i < 422400) { t = 2; start = 115200; C8 = 1024; r = 4; oofs = 1344000L; }
    else                 { t = 3; start = 422400; C8 = 320;  r = 8; oofs = 1651200L; }
    (void)t; (void)C8;
    int li = i - start;
    int OH = 15 * r, OW = 20 * r;
    int oc = li / (OH * OW), rem = li % (OH * OW);
    int oh = rem / OW, ow = rem % OW;
    int ic = oc * r * r + (oh % r) * r + (ow % r);
    out[oofs + li] = x8[start + ic * 300 + (oh / r) * 20 + (ow / r)];
}

// ============================ HMMA GEMM core ============================
// C[M,Ncols] = A[M,K](fp32, split in-kernel) @ B^T, B pre-split bf16 [Npad][K].
// CTA tile 128x64, BK=32, 8 warps (4m x 2n), warp tile 32x32, double buffer.
#define STG 24576
#define GT_SMEM (2 * STG + 1024)

__device__ __forceinline__ void gemm_core(
    char* dsm, const float* __restrict__ A, const __nv_bfloat16* __restrict__ Bh,
    const __nv_bfloat16* __restrict__ Bl, const float* __restrict__ bias,
    float* __restrict__ C, int M, int K, int Ncols, int relu, int m0, int n0) {
    const int tid = threadIdx.x;
    const int lane = tid & 31;
    const int wid = tid >> 5;
    const int wm = wid & 3, wn = wid >> 2;

    const uint32_t base = (smem_u32(dsm) + 1023u) & ~1023u;
    const int bR = tid >> 2, bF = tid & 3;

    uint32_t pA[2], pB[2];
    {
        uint32_t r = (uint32_t)(wm * 32 + (lane & 15));
        uint32_t kc = (uint32_t)((lane >> 4) * 16);
        #pragma unroll
        for (int mt = 0; mt < 2; mt++) {
            uint32_t o = (r + mt * 16) * 64 + kc;
            pA[mt] = o ^ ((o >> 3) & 0x30);
        }
        uint32_t rn = (uint32_t)(wn * 32 + (lane & 7) + ((lane >> 4) << 3));
        uint32_t kcb = (uint32_t)(((lane >> 3) & 1) * 16);
        #pragma unroll
        for (int nt = 0; nt < 2; nt++) {
            uint32_t o = (rn + nt * 16) * 64 + kcb;
            pB[nt] = o ^ ((o >> 3) & 0x30);
        }
    }

    float acc[2][4][4] = {};
    const int nc = K >> 5;

    float4 aP[4];
    uint4 bP[2];
    {
        #pragma unroll
        for (int it = 0; it < 4; it++) {
            int idx = tid + it * 256;
            int row = idx >> 3, f4 = idx & 7;
            int gr = m0 + row;
            aP[it] = (gr < M) ? *reinterpret_cast<const float4*>(A + (size_t)gr * K + f4 * 4)
                              : make_float4(0.f, 0.f, 0.f, 0.f);
        }
        bP[0] = *reinterpret_cast<const uint4*>(Bh + (size_t)(n0 + bR) * K + bF * 8);
        bP[1] = *reinterpret_cast<const uint4*>(Bl + (size_t)(n0 + bR) * K + bF * 8);
    }

    for (int c = 0; c < nc; c++) {
        const uint32_t stg = base + (uint32_t)(c & 1) * STG;
        #pragma unroll
        for (int it = 0; it < 4; it++) {
            int idx = tid + it * 256;
            int row = idx >> 3, f4 = idx & 7;
            float4 v = aP[it];
            __nv_bfloat16 h0 = __float2bfloat16(v.x), h1 = __float2bfloat16(v.y),
                          h2 = __float2bfloat16(v.z), h3 = __float2bfloat16(v.w);
            float l0 = v.x - __bfloat162float(h0), l1 = v.y - __bfloat162float(h1);
            float l2 = v.z - __bfloat162float(h2), l3 = v.w - __bfloat162float(h3);
            uint32_t off = swz64((uint32_t)(row * 64 + f4 * 8));
            sts64(stg + off, packbf2(__bfloat162float(h0), __bfloat162float(h1)),
                             packbf2(__bfloat162float(h2), __bfloat162float(h3)));
            sts64(stg + 8192u + off, packbf2(l0, l1), packbf2(l2, l3));
        }
        {
            uint32_t off = swz64((uint32_t)(bR * 64 + bF * 16));
            sts128(stg + 16384u + off, bP[0]);
            sts128(stg + 20480u + off, bP[1]);
        }
        __syncthreads();
        if (c + 1 < nc) {
            const int k0 = (c + 1) << 5;
            #pragma unroll
            for (int it = 0; it < 4; it++) {
                int idx = tid + it * 256;
                int row = idx >> 3, f4 = idx & 7;
                int gr = m0 + row;
                aP[it] = (gr < M)
                    ? *reinterpret_cast<const float4*>(A + (size_t)gr * K + k0 + f4 * 4)
                    : make_float4(0.f, 0.f, 0.f, 0.f);
            }
            bP[0] = *reinterpret_cast<const uint4*>(Bh + (size_t)(n0 + bR) * K + k0 + bF * 8);
            bP[1] = *reinterpret_cast<const uint4*>(Bl + (size_t)(n0 + bR) * K + k0 + bF * 8);
        }
        #pragma unroll
        for (int ks = 0; ks < 2; ks++) {
            const uint32_t kb = (uint32_t)(ks << 5);
            uint32_t ah[2][4], al[2][4], bh_[2][4], bl_[2][4];
            ldm4(ah[0], stg + (pA[0] ^ kb));
            ldm4(ah[1], stg + (pA[1] ^ kb));
            ldm4(al[0], stg + 8192u + (pA[0] ^ kb));
            ldm4(al[1], stg + 8192u + (pA[1] ^ kb));
            ldm4(bh_[0], stg + 16384u + (pB[0] ^ kb));
            ldm4(bh_[1], stg + 16384u + (pB[1] ^ kb));
            ldm4(bl_[0], stg + 20480u + (pB[0] ^ kb));
            ldm4(bl_[1], stg + 20480u + (pB[1] ^ kb));
            #pragma unroll
            for (int mt = 0; mt < 2; mt++)
                #pragma unroll
                for (int nt = 0; nt < 4; nt++) {
                    const uint32_t* bh2 = &bh_[nt >> 1][(nt & 1) * 2];
                    const uint32_t* bl2 = &bl_[nt >> 1][(nt & 1) * 2];
                    mma_bf16(acc[mt][nt], ah[mt], bh2);
                    mma_bf16(acc[mt][nt], ah[mt], bl2);
                    mma_bf16(acc[mt][nt], al[mt], bh2);
                }
        }
        __syncthreads();
    }

    #pragma unroll
    for (int mt = 0; mt < 2; mt++) {
        int r0 = m0 + wm * 32 + mt * 16 + (lane >> 2);
        #pragma unroll
        for (int half = 0; half < 2; half++) {
            int row = r0 + half * 8;
            if (row >= M) continue;
            float bv = bias[row];
            #pragma unroll
            for (int nt = 0; nt < 4; nt++) {
                int col = n0 + wn * 32 + nt * 8 + (lane & 3) * 2;
                float v0 = acc[mt][nt][half * 2 + 0] + bv;
                float v1 = acc[mt][nt][half * 2 + 1] + bv;
                if (relu) { v0 = fmaxf(v0, 0.f); v1 = fmaxf(v1, 0.f); }
                if (col < Ncols) C[(size_t)row * Ncols + col] = v0;
                if (col + 1 < Ncols) C[(size_t)row * Ncols + col + 1] = v1;
            }
        }
    }
}

__global__ __launch_bounds__(256, 2) void k_gemm_tc(
    const float* __restrict__ A, const __nv_bfloat16* __restrict__ Bh,
    const __nv_bfloat16* __restrict__ Bl, const float* __restrict__ bias,
    float* __restrict__ C, int M, int K, int Ncols, int relu) {
    extern __shared__ char dsm[];
    gemm_core(dsm, A, Bh, Bl, bias, C, M, K, Ncols, relu,
              blockIdx.y * 128, blockIdx.x * 64);
}

// batched 4-branch GEMM: per-z A/bias/B/C/M
struct B4Args {
    const float* A[4];
    const float* bias[4];
    const __nv_bfloat16* Bh[4];
    const __nv_bfloat16* Bl[4];
    float* C[4];
    int M[4];
};
__global__ __launch_bounds__(256, 2) void k_gemm_b4(B4Args args, int K, int Ncols, int relu) {
    extern __shared__ char dsm[];
    const int z = blockIdx.z;
    const int m0 = blockIdx.y * 128;
    if (m0 >= args.M[z]) return;
    gemm_core(dsm, args.A[z], args.Bh[z], args.Bl[z], args.bias[z], args.C[z],
              args.M[z], K, Ncols, relu, m0, blockIdx.x * 64);
}

static inline dim3 blk1(long n) { return dim3((unsigned)((n + 255) / 256)); }

extern "C" void kernel_launch(void* const* d_in, const int* in_sizes, int n_in,
                              void* d_out, int out_size) {
    const float* x  = (const float*)d_in[0];
    const float* w1 = (const float*)d_in[1];  const float* b1 = (const float*)d_in[2];
    const float* w2 = (const float*)d_in[3];  const float* b2 = (const float*)d_in[4];
    const float* w3 = (const float*)d_in[5];  const float* b3 = (const float*)d_in[6];
    const float* w4 = (const float*)d_in[7];  const float* b4 = (const float*)d_in[8];
    const float* w5 = (const float*)d_in[9];  const float* b5 = (const float*)d_in[10];
    const float* w6 = (const float*)d_in[11]; const float* b6 = (const float*)d_in[12];
    const float* w7[4] = {(const float*)d_in[13], (const float*)d_in[17],
                          (const float*)d_in[21], (const float*)d_in[25]};
    const float* b7[4] = {(const float*)d_in[14], (const float*)d_in[18],
                          (const float*)d_in[22], (const float*)d_in[26]};
    const float* w8[4] = {(const float*)d_in[15], (const float*)d_in[19],
                          (const float*)d_in[23], (const float*)d_in[27]};
    const float* b8[4] = {(const float*)d_in[16], (const float*)d_in[20],
                          (const float*)d_in[24], (const float*)d_in[28]};
    float* out = (float*)d_out;

    cudaFuncSetAttribute(k_gemm_tc, cudaFuncAttributeMaxDynamicSharedMemorySize, GT_SMEM);
    cudaFuncSetAttribute(k_gemm_b4, cudaFuncAttributeMaxDynamicSharedMemorySize, GT_SMEM);

    float *c1, *l1, *u1, *c2, *l2, *p2, *c3, *c4, *c5, *p5, *x7, *x8;
    __nv_bfloat16 *bh, *bl, *b6h, *b6l;
    cudaGetSymbolAddress((void**)&c1, g_c1);
    cudaGetSymbolAddress((void**)&l1, g_l1);
    cudaGetSymbolAddress((void**)&u1, g_u1);
    cudaGetSymbolAddress((void**)&c2, g_c2);
    cudaGetSymbolAddress((void**)&l2, g_l2);
    cudaGetSymbolAddress((void**)&p2, g_p2);
    cudaGetSymbolAddress((void**)&c3, g_c3);
    cudaGetSymbolAddress((void**)&c4, g_c4);
    cudaGetSymbolAddress((void**)&c5, g_c5);
    cudaGetSymbolAddress((void**)&p5, g_p5);
    cudaGetSymbolAddress((void**)&x7, g_x7);
    cudaGetSymbolAddress((void**)&x8, g_x8);
    cudaGetSymbolAddress((void**)&bh, gB_hi);
    cudaGetSymbolAddress((void**)&bl, gB_lo);
    cudaGetSymbolAddress((void**)&b6h, gB6_hi);
    cudaGetSymbolAddress((void**)&b6l, gB6_lo);

    // stage 1 (direct fp32)
    k_conv1<<<blk1(96L * 118 * 158), 256>>>(x, w1, b1, c1);
    k_lrn<<<blk1(96L * 118 * 158), 256>>>(c1, l1, 96, 118 * 158, 2.0f, 0.0001f);
    k_poolup<<<blk1(96L * 59 * 79), 256>>>(l1, u1);

    // conv2: M=256 K=2400 N=4661 (Npad 4672)
    k_prepB<<<blk1(4672L * 2400), 256>>>(u1, bh, bl, 96, 59, 79, 5, 2, 59, 79,
                                         2400, 4672L * 2400);
    k_gemm_tc<<<dim3(73, 2), 256, GT_SMEM>>>(w2, bh, bl, b2, c2, 256, 2400, 4661, 1);
    k_lrn<<<blk1(256L * 4661), 256>>>(c2, l2, 256, 4661, 8.0f, 0.0001f);
    k_pool<<<blk1(256L * 29 * 39), 256>>>(l2, p2, 256, 59, 79, 29, 39);

    // conv3: M=384 K=2304 N=1131 (Npad 1152)
    k_prepB<<<blk1(1152L * 2304), 256>>>(p2, bh, bl, 256, 29, 39, 3, 1, 29, 39,
                                         2304, 1152L * 2304);
    k_gemm_tc<<<dim3(18, 3), 256, GT_SMEM>>>(w3, bh, bl, b3, c3, 384, 2304, 1131, 1);
    // conv4: K=3456
    k_prepB<<<blk1(1152L * 3456), 256>>>(c3, bh, bl, 384, 29, 39, 3, 1, 29, 39,
                                         3456, 1152L * 3456);
    k_gemm_tc<<<dim3(18, 3), 256, GT_SMEM>>>(w4, bh, bl, b4, c4, 384, 3456, 1131, 1);
    // conv5
    k_prepB<<<blk1(1152L * 3456), 256>>>(c4, bh, bl, 384, 29, 39, 3, 1, 29, 39,
                                         3456, 1152L * 3456);
    k_gemm_tc<<<dim3(18, 3), 256, GT_SMEM>>>(w5, bh, bl, b5, c5, 384, 3456, 1131, 1);
    k_pool<<<blk1(384L * 14 * 19), 256>>>(c5, p5, 384, 29, 39, 14, 19);

    // conv6: M=4096 K=13824 N=300 (Npad 320) -> x6 straight into d_out
    k_prepB<<<blk1(320L * 13824), 256>>>(p5, bh, bl, 384, 14, 19, 6, 3, 15, 20,
                                         13824, 320L * 13824);
    k_gemm_tc<<<dim3(5, 32), 256, GT_SMEM>>>(w6, bh, bl, b6, out, 4096, 13824, 300, 1);

    // split x6 once (1x1 conv: C=4096 over 15x20)
    k_prepB<<<blk1(320L * 4096), 256>>>(out, b6h, b6l, 4096, 15, 20, 1, 0, 15, 20,
                                        4096, 320L * 4096);

    // ---- batched branch phase ----
    // gemm7 (all 4): x7buf[z] = relu(w7[z] @ x6_split + b7[z])
    B4Args a7;
    for (int t = 0; t < 4; t++) {
        a7.A[t] = w7[t]; a7.bias[t] = b7[t];
        a7.Bh[t] = b6h;  a7.Bl[t] = b6l;
        a7.C[t] = x7 + (size_t)t * 4096 * 300;
        a7.M[t] = 4096;
    }
    k_gemm_b4<<<dim3(5, 32, 4), 256, GT_SMEM>>>(a7, 4096, 300, 1);

    // split all four x7 tensors
    k_prep7b<<<blk1(4L * 320 * 4096), 256>>>(x7, bh, bl);

    // gemm8 (all 4): x8 rows packed [256 | 128 | 1024 | 320]
    const int  C8s[4] = {256, 128, 1024, 320};
    const long rowoff8[4] = {0, 256, 384, 1408};
    B4Args a8;
    for (int t = 0; t < 4; t++) {
        a8.A[t] = w8[t]; a8.bias[t] = b8[t];
        a8.Bh[t] = bh + (size_t)t * 320 * 4096;
        a8.Bl[t] = bl + (size_t)t * 320 * 4096;
        a8.C[t] = x8 + rowoff8[t] * 300;
        a8.M[t] = C8s[t];
    }
    k_gemm_b4<<<dim3(5, 8, 4), 256, GT_SMEM>>>(a8, 4096, 300, 0);

    // fused pixel-shuffle for all branches
    k_tile4<<<blk1(518400L), 256>>>(x8, out);
}

// round 5
// speedup vs baseline: 1.0207x; 1.0207x over previous
#include <cuda_runtime.h>
#include <cuda_bf16.h>
#include <math.h>
#include <stdint.h>

// ---------------------------------------------------------------------------
// VPGNet forward. Conv GEMMs via warp-level mma.sync bf16 (2-term split,
// fp32 accumulate). Split-K + batched branches for occupancy.
// Output: [x6 | x8a | x8b | x8c | x8d] = 1,747,200 floats
// ---------------------------------------------------------------------------

// ---- scratch (__device__ globals: no allocation allowed) ----
__device__ float g_c1[96 * 118 * 158];
__device__ float g_l1[96 * 118 * 158];
__device__ float g_u1[96 * 59 * 79];
__device__ float g_c2[256 * 59 * 79];
__device__ float g_l2[256 * 59 * 79];
__device__ float g_p2[256 * 29 * 39];
__device__ float g_c3[384 * 29 * 39];
__device__ float g_c4[384 * 29 * 39];
__device__ float g_c5[384 * 29 * 39];
__device__ float g_p5[384 * 14 * 19];
__device__ float g_x7[4 * 4096 * 300];
__device__ float g_x8[1728 * 300];
// split-K partial buffers
__device__ float g_p6[4 * 4096 * 300];        // conv6, 4 slices
__device__ float g_p7[2 * 4 * 4096 * 300];    // gemm7, 2 slices x 4 branches
__device__ float g_p8[4 * 1728 * 300];        // gemm8, 4 slices (packed rows)
// bf16 split activation buffers [Npad][K]; max conv2: 4672*2400 = 11,212,800
// (also reused for the 4 branch x7 splits: 4 * 320*4096 = 5,242,880)
__device__ __nv_bfloat16 gB_hi[11250000];
__device__ __nv_bfloat16 gB_lo[11250000];
// dedicated split of x6 (shared by all 4 branch gemm7s)
__device__ __nv_bfloat16 gB6_hi[320 * 4096];
__device__ __nv_bfloat16 gB6_lo[320 * 4096];

// ============================ helpers ============================
__device__ __forceinline__ uint32_t smem_u32(const void* p) {
    uint32_t a;
    asm("{ .reg .u64 t; cvta.to.shared.u64 t, %1; cvt.u32.u64 %0, t; }" : "=r"(a) : "l"(p));
    return a;
}
__device__ __forceinline__ uint32_t swz64(uint32_t o) { return o ^ ((o >> 3) & 0x30); }

__device__ __forceinline__ void ldm4(uint32_t* r, uint32_t a) {
    asm volatile("ldmatrix.sync.aligned.m8n8.x4.shared.b16 {%0,%1,%2,%3}, [%4];"
                 : "=r"(r[0]), "=r"(r[1]), "=r"(r[2]), "=r"(r[3]) : "r"(a));
}
__device__ __forceinline__ void mma_bf16(float* c, const uint32_t* a, const uint32_t* b) {
    asm volatile("mma.sync.aligned.m16n8k16.row.col.f32.bf16.bf16.f32 "
                 "{%0,%1,%2,%3}, {%4,%5,%6,%7}, {%8,%9}, {%0,%1,%2,%3};"
                 : "+f"(c[0]), "+f"(c[1]), "+f"(c[2]), "+f"(c[3])
                 : "r"(a[0]), "r"(a[1]), "r"(a[2]), "r"(a[3]), "r"(b[0]), "r"(b[1]));
}
__device__ __forceinline__ void sts128(uint32_t a, uint4 v) {
    asm volatile("st.shared.v4.b32 [%0], {%1,%2,%3,%4};"
                 :: "r"(a), "r"(v.x), "r"(v.y), "r"(v.z), "r"(v.w) : "memory");
}
__device__ __forceinline__ void sts64(uint32_t a, uint32_t x, uint32_t y) {
    asm volatile("st.shared.v2.b32 [%0], {%1,%2};" :: "r"(a), "r"(x), "r"(y) : "memory");
}
__device__ __forceinline__ uint32_t packbf2(float lo, float hi) {
    uint32_t d;
    asm("cvt.rn.bf16x2.f32 %0, %1, %2;" : "=r"(d) : "f"(hi), "f"(lo));
    return d;
}

// ============================ small layers ============================
__global__ void k_conv1(const float* __restrict__ x, const float* __restrict__ w,
                        const float* __restrict__ b, float* __restrict__ out) {
    const int HO = 118, WO = 158;
    int i = blockIdx.x * blockDim.x + threadIdx.x;
    if (i >= 96 * HO * WO) return;
    int c = i / (HO * WO), r = i % (HO * WO), oh = r / WO, ow = r % WO;
    float acc = b[c];
    const float* wp = w + c * 3 * 121;
    for (int ci = 0; ci < 3; ci++) {
        const float* xc = x + ci * 480 * 640;
        const float* wc = wp + ci * 121;
        #pragma unroll
        for (int kh = 0; kh < 11; kh++) {
            const float* xp = xc + (oh * 4 + kh) * 640 + ow * 4;
            const float* wq = wc + kh * 11;
            #pragma unroll
            for (int kw = 0; kw < 11; kw++) acc = fmaf(xp[kw], wq[kw], acc);
        }
    }
    out[i] = fmaxf(acc, 0.f);
}

__global__ void k_lrn(const float* __restrict__ in, float* __restrict__ out,
                      int C, int HW, float kconst, float a) {
    int i = blockIdx.x * blockDim.x + threadIdx.x;
    if (i >= C * HW) return;
    int c = i / HW, s = i % HW;
    int lo = c - 2 > 0 ? c - 2 : 0;
    int hi = c + 2 < C - 1 ? c + 2 : C - 1;
    float sum = 0.f;
    for (int j = lo; j <= hi; j++) { float v = in[j * HW + s]; sum = fmaf(v, v, sum); }
    float t = kconst + a * sum;
    float r = rsqrtf(t);
    out[i] = in[i] * r * sqrtf(r);       // t^-0.75
}

__global__ void k_poolup(const float* __restrict__ in, float* __restrict__ out) {
    int i = blockIdx.x * blockDim.x + threadIdx.x;
    if (i >= 96 * 59 * 79) return;
    int c = i / (59 * 79), r = i % (59 * 79), oh = r / 79, ow = r % 79;
    int hi = (oh * 58) / 59, wi = (ow * 78) / 79;
    const float* p = in + (c * 118 + 2 * hi) * 158 + 2 * wi;
    float m = p[0];
    #pragma unroll
    for (int dh = 0; dh < 3; dh++)
        #pragma unroll
        for (int dw = 0; dw < 3; dw++) m = fmaxf(m, p[dh * 158 + dw]);
    out[i] = m;
}

__global__ void k_pool(const float* __restrict__ in, float* __restrict__ out,
                       int C, int Hin, int Win, int Ho, int Wo) {
    int i = blockIdx.x * blockDim.x + threadIdx.x;
    if (i >= C * Ho * Wo) return;
    int c = i / (Ho * Wo), r = i % (Ho * Wo), oh = r / Wo, ow = r % Wo;
    const float* p = in + (c * Hin + 2 * oh) * Win + 2 * ow;
    float m = p[0];
    #pragma unroll
    for (int dh = 0; dh < 3; dh++)
        #pragma unroll
        for (int dw = 0; dw < 3; dw++) m = fmaxf(m, p[dh * Win + dw]);
    out[i] = m;
}

// ---- im2col + transpose + bf16 split, 2D grid (no 64-bit div/mod) ----
// grid: x covers K (256/blk), y = padded spatial index n. out row-major [Npad][K].
__global__ void k_prepB2d(const float* __restrict__ src, __nv_bfloat16* __restrict__ hi,
                          __nv_bfloat16* __restrict__ lo, int H, int W,
                          int ksz, int pad, int Ho, int Wo, int K) {
    int kidx = blockIdx.x * 256 + threadIdx.x;
    if (kidx >= K) return;
    int n = blockIdx.y;
    float v = 0.f;
    if (n < Ho * Wo) {
        int kw = kidx % ksz;
        int t = kidx / ksz;
        int kh = t % ksz, cc = t / ksz;
        int oh = n / Wo, ow = n % Wo;
        int ih = oh - pad + kh, iw = ow - pad + kw;
        if (ih >= 0 && ih < H && iw >= 0 && iw < W) v = src[((size_t)cc * H + ih) * W + iw];
    }
    size_t o = (size_t)n * K + kidx;
    __nv_bfloat16 h = __float2bfloat16(v);
    hi[o] = h;
    lo[o] = __float2bfloat16(v - __bfloat162float(h));
}

// ---- batched split of the four x7 tensors (K=4096, N=300, Npad=320) ----
__global__ void k_prep7b(const float* __restrict__ x7, __nv_bfloat16* __restrict__ hi,
                         __nv_bfloat16* __restrict__ lo) {
    int z = blockIdx.y;
    int i = blockIdx.x * 256 + threadIdx.x;       // 0 .. 320*4096-1
    int n = i >> 12, k = i & 4095;
    float v = 0.f;
    if (n < 300) v = x7[(size_t)z * 1228800 + (size_t)k * 300 + n];
    __nv_bfloat16 h = __float2bfloat16(v);
    size_t o = (size_t)z * 1310720 + i;
    hi[o] = h;
    lo[o] = __float2bfloat16(v - __bfloat162float(h));
}

// ---- fused 4-branch pixel-shuffle tile ----
__global__ void k_tile4(const float* __restrict__ x8, float* __restrict__ out) {
    int i = blockIdx.x * blockDim.x + threadIdx.x;
    if (i >= 518400) return;
    int start, r;
    long oofs;
    if (i < 76800)       { start = 0;      r = 8; oofs = 1228800L; }
    else if (i < 115200) { start = 76800;  r = 8; oofs = 1305600L; }
    else if (i < 422400) { start = 115200; r = 4; oofs = 1344000L; }
    else                 { start = 422400; r = 8; oofs = 1651200L; }
    int li = i - start;
    int OW = 20 * r;
    int OHW = 300 * r * r;
    int oc = li / OHW, rem = li % OHW;
    int oh = rem / OW, ow = rem % OW;
    int ic = oc * r * r + (oh % r) * r + (ow % r);
    out[oofs + li] = x8[start + ic * 300 + (oh / r) * 20 + (ow / r)];
}

// ---- split-K reduce kernels ----
__global__ void k_red6(const float* __restrict__ p, const float* __restrict__ bias,
                       float* __restrict__ out) {
    int i = blockIdx.x * blockDim.x + threadIdx.x;
    if (i >= 4096 * 300) return;
    float v = p[i] + p[i + 1228800] + p[i + 2 * 1228800] + p[i + 3 * 1228800];
    out[i] = fmaxf(v + bias[i / 300], 0.f);
}
struct Bias4 { const float* b[4]; };
__global__ void k_red7(const float* __restrict__ p, Bias4 bias, float* __restrict__ out) {
    int z = blockIdx.y;
    int i = blockIdx.x * blockDim.x + threadIdx.x;
    if (i >= 4096 * 300) return;
    size_t o = (size_t)z * 1228800 + i;
    float v = p[o] + p[o + 4 * 1228800];
    out[o] = fmaxf(v + bias.b[z][i / 300], 0.f);
}
__global__ void k_red8(const float* __restrict__ p, Bias4 bias, float* __restrict__ out) {
    int i = blockIdx.x * blockDim.x + threadIdx.x;
    if (i >= 518400) return;
    float v = p[i] + p[i + 518400] + p[i + 2 * 518400] + p[i + 3 * 518400];
    int row = i / 300;
    float bv;
    if (row < 256)       bv = bias.b[0][row];
    else if (row < 384)  bv = bias.b[1][row - 256];
    else if (row < 1408) bv = bias.b[2][row - 384];
    else                 bv = bias.b[3][row - 1408];
    out[i] = v + bv;
}

// ============================ HMMA GEMM core ============================
// C[M,Ncols] partial/full = A[M,K](fp32, split in-kernel) @ B^T over chunk
// range [c0,cEnd). B pre-split bf16 [Npad][K]. CTA tile 128x64, BK=32,
// 8 warps (4m x 2n), double buffer. bias==nullptr -> raw partial store.
#define STG 24576
#define GT_SMEM (2 * STG + 1024)

__device__ __forceinline__ void gemm_core(
    char* dsm, const float* __restrict__ A, const __nv_bfloat16* __restrict__ Bh,
    const __nv_bfloat16* __restrict__ Bl, const float* __restrict__ bias,
    float* __restrict__ C, int M, int K, int Ncols, int relu, int m0, int n0,
    int c0, int cEnd) {
    const int tid = threadIdx.x;
    const int lane = tid & 31;
    const int wid = tid >> 5;
    const int wm = wid & 3, wn = wid >> 2;

    const uint32_t base = (smem_u32(dsm) + 1023u) & ~1023u;
    const int bR = tid >> 2, bF = tid & 3;

    uint32_t pA[2], pB[2];
    {
        uint32_t r = (uint32_t)(wm * 32 + (lane & 15));
        uint32_t kc = (uint32_t)((lane >> 4) * 16);
        #pragma unroll
        for (int mt = 0; mt < 2; mt++) {
            uint32_t o = (r + mt * 16) * 64 + kc;
            pA[mt] = o ^ ((o >> 3) & 0x30);
        }
        uint32_t rn = (uint32_t)(wn * 32 + (lane & 7) + ((lane >> 4) << 3));
        uint32_t kcb = (uint32_t)(((lane >> 3) & 1) * 16);
        #pragma unroll
        for (int nt = 0; nt < 2; nt++) {
            uint32_t o = (rn + nt * 16) * 64 + kcb;
            pB[nt] = o ^ ((o >> 3) & 0x30);
        }
    }

    float acc[2][4][4] = {};

    float4 aP[4];
    uint4 bP[2];
    {
        const int k0 = c0 << 5;
        #pragma unroll
        for (int it = 0; it < 4; it++) {
            int idx = tid + it * 256;
            int row = idx >> 3, f4 = idx & 7;
            int gr = m0 + row;
            aP[it] = (gr < M)
                ? *reinterpret_cast<const float4*>(A + (size_t)gr * K + k0 + f4 * 4)
                : make_float4(0.f, 0.f, 0.f, 0.f);
        }
        bP[0] = *reinterpret_cast<const uint4*>(Bh + (size_t)(n0 + bR) * K + k0 + bF * 8);
        bP[1] = *reinterpret_cast<const uint4*>(Bl + (size_t)(n0 + bR) * K + k0 + bF * 8);
    }

    for (int c = c0; c < cEnd; c++) {
        const uint32_t stg = base + (uint32_t)(c & 1) * STG;
        #pragma unroll
        for (int it = 0; it < 4; it++) {
            int idx = tid + it * 256;
            int row = idx >> 3, f4 = idx & 7;
            float4 v = aP[it];
            __nv_bfloat16 h0 = __float2bfloat16(v.x), h1 = __float2bfloat16(v.y),
                          h2 = __float2bfloat16(v.z), h3 = __float2bfloat16(v.w);
            float l0 = v.x - __bfloat162float(h0), l1 = v.y - __bfloat162float(h1);
            float l2 = v.z - __bfloat162float(h2), l3 = v.w - __bfloat162float(h3);
            uint32_t off = swz64((uint32_t)(row * 64 + f4 * 8));
            sts64(stg + off, packbf2(__bfloat162float(h0), __bfloat162float(h1)),
                             packbf2(__bfloat162float(h2), __bfloat162float(h3)));
            sts64(stg + 8192u + off, packbf2(l0, l1), packbf2(l2, l3));
        }
        {
            uint32_t off = swz64((uint32_t)(bR * 64 + bF * 16));
            sts128(stg + 16384u + off, bP[0]);
            sts128(stg + 20480u + off, bP[1]);
        }
        __syncthreads();
        if (c + 1 < cEnd) {
            const int k0 = (c + 1) << 5;
            #pragma unroll
            for (int it = 0; it < 4; it++) {
                int idx = tid + it * 256;
                int row = idx >> 3, f4 = idx & 7;
                int gr = m0 + row;
                aP[it] = (gr < M)
                    ? *reinterpret_cast<const float4*>(A + (size_t)gr * K + k0 + f4 * 4)
                    : make_float4(0.f, 0.f, 0.f, 0.f);
            }
            bP[0] = *reinterpret_cast<const uint4*>(Bh + (size_t)(n0 + bR) * K + k0 + bF * 8);
            bP[1] = *reinterpret_cast<const uint4*>(Bl + (size_t)(n0 + bR) * K + k0 + bF * 8);
        }
        #pragma unroll
        for (int ks = 0; ks < 2; ks++) {
            const uint32_t kb = (uint32_t)(ks << 5);
            uint32_t ah[2][4], al[2][4], bh_[2][4], bl_[2][4];
            ldm4(ah[0], stg + (pA[0] ^ kb));
            ldm4(ah[1], stg + (pA[1] ^ kb));
            ldm4(al[0], stg + 8192u + (pA[0] ^ kb));
            ldm4(al[1], stg + 8192u + (pA[1] ^ kb));
            ldm4(bh_[0], stg + 16384u + (pB[0] ^ kb));
            ldm4(bh_[1], stg + 16384u + (pB[1] ^ kb));
            ldm4(bl_[0], stg + 20480u + (pB[0] ^ kb));
            ldm4(bl_[1], stg + 20480u + (pB[1] ^ kb));
            #pragma unroll
            for (int mt = 0; mt < 2; mt++)
                #pragma unroll
                for (int nt = 0; nt < 4; nt++) {
                    const uint32_t* bh2 = &bh_[nt >> 1][(nt & 1) * 2];
                    const uint32_t* bl2 = &bl_[nt >> 1][(nt & 1) * 2];
                    mma_bf16(acc[mt][nt], ah[mt], bh2);
                    mma_bf16(acc[mt][nt], ah[mt], bl2);
                    mma_bf16(acc[mt][nt], al[mt], bh2);
                }
        }
        __syncthreads();
    }

    #pragma unroll
    for (int mt = 0; mt < 2; mt++) {
        int r0 = m0 + wm * 32 + mt * 16 + (lane >> 2);
        #pragma unroll
        for (int half = 0; half < 2; half++) {
            int row = r0 + half * 8;
            if (row >= M) continue;
            float bv = bias ? bias[row] : 0.f;
            #pragma unroll
            for (int nt = 0; nt < 4; nt++) {
                int col = n0 + wn * 32 + nt * 8 + (lane & 3) * 2;
                float v0 = acc[mt][nt][half * 2 + 0] + bv;
                float v1 = acc[mt][nt][half * 2 + 1] + bv;
                if (relu) { v0 = fmaxf(v0, 0.f); v1 = fmaxf(v1, 0.f); }
                if (col < Ncols) C[(size_t)row * Ncols + col] = v0;
                if (col + 1 < Ncols) C[(size_t)row * Ncols + col + 1] = v1;
            }
        }
    }
}

// full-K GEMM with bias (+optional relu): conv2..5
__global__ __launch_bounds__(256, 2) void k_gemm_tc(
    const float* __restrict__ A, const __nv_bfloat16* __restrict__ Bh,
    const __nv_bfloat16* __restrict__ Bl, const float* __restrict__ bias,
    float* __restrict__ C, int M, int K, int Ncols, int relu) {
    extern __shared__ char dsm[];
    gemm_core(dsm, A, Bh, Bl, bias, C, M, K, Ncols, relu,
              blockIdx.y * 128, blockIdx.x * 64, 0, K >> 5);
}

// conv6 split-K=4: z = slice, partial -> g_p6[slice]
__global__ __launch_bounds__(256, 2) void k_gemm_sk6(
    const float* __restrict__ A, const __nv_bfloat16* __restrict__ Bh,
    const __nv_bfloat16* __restrict__ Bl, float* __restrict__ P) {
    extern __shared__ char dsm[];
    const int z = blockIdx.z;                 // 0..3
    const int nc = 13824 >> 5;                // 432
    const int per = nc >> 2;                  // 108
    gemm_core(dsm, A, Bh, Bl, nullptr, P + (size_t)z * 1228800,
              4096, 13824, 300, 0, blockIdx.y * 128, blockIdx.x * 64,
              z * per, (z + 1) * per);
}

// gemm7 split-K=2, batched over 4 branches: z = branch*2 + slice
struct Ptr4 { const float* p[4]; };
__global__ __launch_bounds__(256, 2) void k_gemm7(
    Ptr4 W, const __nv_bfloat16* __restrict__ Bh,
    const __nv_bfloat16* __restrict__ Bl, float* __restrict__ P) {
    extern __shared__ char dsm[];
    const int br = blockIdx.z >> 1, sl = blockIdx.z & 1;
    const int per = 128 >> 1;                 // nc=128, 64 per slice
    float* out = P + (size_t)sl * 4 * 1228800 + (size_t)br * 1228800;
    gemm_core(dsm, W.p[br], Bh, Bl, nullptr, out,
              4096, 4096, 300, 0, blockIdx.y * 128, blockIdx.x * 64,
              sl * per, (sl + 1) * per);
}

// gemm8 split-K=4, batched over 4 branches: z = branch*4 + slice
__global__ __launch_bounds__(256, 2) void k_gemm8(
    Ptr4 W, const __nv_bfloat16* __restrict__ Bh,
    const __nv_bfloat16* __restrict__ Bl, float* __restrict__ P) {
    extern __shared__ char dsm[];
    const int br = blockIdx.z >> 2, sl = blockIdx.z & 3;
    const int C8s[4] = {256, 128, 1024, 320};
    const int roff[4] = {0, 256, 384, 1408};
    const int M = C8s[br];
    const int m0 = blockIdx.y * 128;
    if (m0 >= M) return;
    const int per = 128 >> 2;                 // 32 chunks per slice
    float* out = P + (size_t)sl * 518400 + (size_t)roff[br] * 300;
    gemm_core(dsm, W.p[br], Bh + (size_t)br * 1310720, Bl + (size_t)br * 1310720,
              nullptr, out, M, 4096, 300, 0, m0, blockIdx.x * 64,
              sl * per, (sl + 1) * per);
}

static inline dim3 blk1(long n) { return dim3((unsigned)((n + 255) / 256)); }

extern "C" void kernel_launch(void* const* d_in, const int* in_sizes, int n_in,
                              void* d_out, int out_size) {
    const float* x  = (const float*)d_in[0];
    const float* w1 = (const float*)d_in[1];  const float* b1 = (const float*)d_in[2];
    const float* w2 = (const float*)d_in[3];  const float* b2 = (const float*)d_in[4];
    const float* w3 = (const float*)d_in[5];  const float* b3 = (const float*)d_in[6];
    const float* w4 = (const float*)d_in[7];  const float* b4 = (const float*)d_in[8];
    const float* w5 = (const float*)d_in[9];  const float* b5 = (const float*)d_in[10];
    const float* w6 = (const float*)d_in[11]; const float* b6 = (const float*)d_in[12];
    const float* w7[4] = {(const float*)d_in[13], (const float*)d_in[17],
                          (const float*)d_in[21], (const float*)d_in[25]};
    const float* b7[4] = {(const float*)d_in[14], (const float*)d_in[18],
                          (const float*)d_in[22], (const float*)d_in[26]};
    const float* w8[4] = {(const float*)d_in[15], (const float*)d_in[19],
                          (const float*)d_in[23], (const float*)d_in[27]};
    const float* b8[4] = {(const float*)d_in[16], (const float*)d_in[20],
                          (const float*)d_in[24], (const float*)d_in[28]};
    float* out = (float*)d_out;

    cudaFuncSetAttribute(k_gemm_tc,  cudaFuncAttributeMaxDynamicSharedMemorySize, GT_SMEM);
    cudaFuncSetAttribute(k_gemm_sk6, cudaFuncAttributeMaxDynamicSharedMemorySize, GT_SMEM);
    cudaFuncSetAttribute(k_gemm7,    cudaFuncAttributeMaxDynamicSharedMemorySize, GT_SMEM);
    cudaFuncSetAttribute(k_gemm8,    cudaFuncAttributeMaxDynamicSharedMemorySize, GT_SMEM);

    float *c1, *l1, *u1, *c2, *l2, *p2, *c3, *c4, *c5, *p5, *x7, *x8, *p6, *p7, *p8;
    __nv_bfloat16 *bh, *bl, *b6h, *b6l;
    cudaGetSymbolAddress((void**)&c1, g_c1);
    cudaGetSymbolAddress((void**)&l1, g_l1);
    cudaGetSymbolAddress((void**)&u1, g_u1);
    cudaGetSymbolAddress((void**)&c2, g_c2);
    cudaGetSymbolAddress((void**)&l2, g_l2);
    cudaGetSymbolAddress((void**)&p2, g_p2);
    cudaGetSymbolAddress((void**)&c3, g_c3);
    cudaGetSymbolAddress((void**)&c4, g_c4);
    cudaGetSymbolAddress((void**)&c5, g_c5);
    cudaGetSymbolAddress((void**)&p5, g_p5);
    cudaGetSymbolAddress((void**)&x7, g_x7);
    cudaGetSymbolAddress((void**)&x8, g_x8);
    cudaGetSymbolAddress((void**)&p6, g_p6);
    cudaGetSymbolAddress((void**)&p7, g_p7);
    cudaGetSymbolAddress((void**)&p8, g_p8);
    cudaGetSymbolAddress((void**)&bh, gB_hi);
    cudaGetSymbolAddress((void**)&bl, gB_lo);
    cudaGetSymbolAddress((void**)&b6h, gB6_hi);
    cudaGetSymbolAddress((void**)&b6l, gB6_lo);

    // stage 1 (direct fp32)
    k_conv1<<<blk1(96L * 118 * 158), 256>>>(x, w1, b1, c1);
    k_lrn<<<blk1(96L * 118 * 158), 256>>>(c1, l1, 96, 118 * 158, 2.0f, 0.0001f);
    k_poolup<<<blk1(96L * 59 * 79), 256>>>(l1, u1);

    // conv2: M=256 K=2400 N=4661 (Npad 4672)
    k_prepB2d<<<dim3(10, 4672), 256>>>(u1, bh, bl, 59, 79, 5, 2, 59, 79, 2400);
    k_gemm_tc<<<dim3(73, 2), 256, GT_SMEM>>>(w2, bh, bl, b2, c2, 256, 2400, 4661, 1);
    k_lrn<<<blk1(256L * 4661), 256>>>(c2, l2, 256, 4661, 8.0f, 0.0001f);
    k_pool<<<blk1(256L * 29 * 39), 256>>>(l2, p2, 256, 59, 79, 29, 39);

    // conv3: M=384 K=2304 N=1131 (Npad 1152)
    k_prepB2d<<<dim3(9, 1152), 256>>>(p2, bh, bl, 29, 39, 3, 1, 29, 39, 2304);
    k_gemm_tc<<<dim3(18, 3), 256, GT_SMEM>>>(w3, bh, bl, b3, c3, 384, 2304, 1131, 1);
    // conv4: K=3456
    k_prepB2d<<<dim3(14, 1152), 256>>>(c3, bh, bl, 29, 39, 3, 1, 29, 39, 3456);
    k_gemm_tc<<<dim3(18, 3), 256, GT_SMEM>>>(w4, bh, bl, b4, c4, 384, 3456, 1131, 1);
    // conv5
    k_prepB2d<<<dim3(14, 1152), 256>>>(c4, bh, bl, 29, 39, 3, 1, 29, 39, 3456);
    k_gemm_tc<<<dim3(18, 3), 256, GT_SMEM>>>(w5, bh, bl, b5, c5, 384, 3456, 1131, 1);
    k_pool<<<blk1(384L * 14 * 19), 256>>>(c5, p5, 384, 29, 39, 14, 19);

    // conv6: M=4096 K=13824 N=300 (Npad 320), split-K=4 -> reduce into d_out
    k_prepB2d<<<dim3(54, 320), 256>>>(p5, bh, bl, 14, 19, 6, 3, 15, 20, 13824);
    k_gemm_sk6<<<dim3(5, 32, 4), 256, GT_SMEM>>>(w6, bh, bl, p6);
    k_red6<<<blk1(4096L * 300), 256>>>(p6, b6, out);

    // split x6 once (1x1 conv layout)
    k_prepB2d<<<dim3(16, 320), 256>>>(out, b6h, b6l, 15, 20, 1, 0, 15, 20, 4096);

    // gemm7: all 4 branches, split-K=2 -> partials -> reduce into x7
    Ptr4 W7 = {{w7[0], w7[1], w7[2], w7[3]}};
    k_gemm7<<<dim3(5, 32, 8), 256, GT_SMEM>>>(W7, b6h, b6l, p7);
    Bias4 B7 = {{b7[0], b7[1], b7[2], b7[3]}};
    k_red7<<<dim3((unsigned)((1228800 + 255) / 256), 4), 256>>>(p7, B7, x7);

    // split all four x7 tensors
    k_prep7b<<<dim3(5120, 4), 256>>>(x7, bh, bl);

    // gemm8: all 4 branches packed [256|128|1024|320], split-K=4 -> reduce
    Ptr4 W8 = {{w8[0], w8[1], w8[2], w8[3]}};
    k_gemm8<<<dim3(5, 8, 16), 256, GT_SMEM>>>(W8, bh, bl, p8);
    Bias4 B8 = {{b8[0], b8[1], b8[2], b8[3]}};
    k_red8<<<blk1(518400L), 256>>>(p8, B8, x8);

    // fused pixel-shuffle for all branches
    k_tile4<<<blk1(518400L), 256>>>(x8, out);
}

// round 6
// speedup vs baseline: 1.7352x; 1.7001x over previous
#include <cuda_runtime.h>
#include <cuda_bf16.h>
#include <math.h>
#include <stdint.h>

// ---------------------------------------------------------------------------
// VPGNet forward. Conv GEMMs via warp-level mma.sync bf16 (2-term split,
// fp32 accumulate). Split-K + batched branches. Single-barrier double buffer.
// Output: [x6 | x8a | x8b | x8c | x8d] = 1,747,200 floats
// ---------------------------------------------------------------------------

// ---- scratch (__device__ globals: no allocation allowed) ----
__device__ float g_c1[96 * 118 * 158];
__device__ float g_u1[96 * 59 * 79];
__device__ float g_c2[256 * 59 * 79];
__device__ float g_l2[256 * 59 * 79];
__device__ float g_p2[256 * 29 * 39];
__device__ float g_c3[384 * 29 * 39];
__device__ float g_c4[384 * 29 * 39];
__device__ float g_c5[384 * 29 * 39];
__device__ float g_p5[384 * 14 * 19];
__device__ float g_x7[4 * 4096 * 300];
__device__ float g_x8[1728 * 300];
// split-K partial buffers
__device__ float g_p6[4 * 4096 * 300];        // conv6, 4 slices
__device__ float g_p7[2 * 4 * 4096 * 300];    // gemm7, 2 slices x 4 branches
__device__ float g_p8[4 * 1728 * 300];        // gemm8, 4 slices (packed rows)
// bf16 split activation buffers [Npad][K]; max conv2: 4672*2400 = 11,212,800
// (also reused for the 4 branch x7 splits: 4 * 320*4096 = 5,242,880)
__device__ __nv_bfloat16 gB_hi[11250000];
__device__ __nv_bfloat16 gB_lo[11250000];
// dedicated split of x6 (shared by all 4 branch gemm7s)
__device__ __nv_bfloat16 gB6_hi[320 * 4096];
__device__ __nv_bfloat16 gB6_lo[320 * 4096];

// ============================ helpers ============================
__device__ __forceinline__ uint32_t smem_u32(const void* p) {
    uint32_t a;
    asm("{ .reg .u64 t; cvta.to.shared.u64 t, %1; cvt.u32.u64 %0, t; }" : "=r"(a) : "l"(p));
    return a;
}
__device__ __forceinline__ uint32_t swz64(uint32_t o) { return o ^ ((o >> 3) & 0x30); }

__device__ __forceinline__ void ldm4(uint32_t* r, uint32_t a) {
    asm volatile("ldmatrix.sync.aligned.m8n8.x4.shared.b16 {%0,%1,%2,%3}, [%4];"
                 : "=r"(r[0]), "=r"(r[1]), "=r"(r[2]), "=r"(r[3]) : "r"(a));
}
__device__ __forceinline__ void mma_bf16(float* c, const uint32_t* a, const uint32_t* b) {
    asm volatile("mma.sync.aligned.m16n8k16.row.col.f32.bf16.bf16.f32 "
                 "{%0,%1,%2,%3}, {%4,%5,%6,%7}, {%8,%9}, {%0,%1,%2,%3};"
                 : "+f"(c[0]), "+f"(c[1]), "+f"(c[2]), "+f"(c[3])
                 : "r"(a[0]), "r"(a[1]), "r"(a[2]), "r"(a[3]), "r"(b[0]), "r"(b[1]));
}
__device__ __forceinline__ void sts128(uint32_t a, uint4 v) {
    asm volatile("st.shared.v4.b32 [%0], {%1,%2,%3,%4};"
                 :: "r"(a), "r"(v.x), "r"(v.y), "r"(v.z), "r"(v.w) : "memory");
}
__device__ __forceinline__ void sts64(uint32_t a, uint32_t x, uint32_t y) {
    asm volatile("st.shared.v2.b32 [%0], {%1,%2};" :: "r"(a), "r"(x), "r"(y) : "memory");
}
__device__ __forceinline__ uint32_t packbf2(float lo, float hi) {
    uint32_t d;
    asm("cvt.rn.bf16x2.f32 %0, %1, %2;" : "=r"(d) : "f"(hi), "f"(lo));
    return d;
}

// ============================ small layers ============================
__global__ void k_conv1(const float* __restrict__ x, const float* __restrict__ w,
                        const float* __restrict__ b, float* __restrict__ out) {
    const int HO = 118, WO = 158;
    int i = blockIdx.x * blockDim.x + threadIdx.x;
    if (i >= 96 * HO * WO) return;
    int c = i / (HO * WO), r = i % (HO * WO), oh = r / WO, ow = r % WO;
    float acc = b[c];
    const float* wp = w + c * 3 * 121;
    for (int ci = 0; ci < 3; ci++) {
        const float* xc = x + ci * 480 * 640;
        const float* wc = wp + ci * 121;
        #pragma unroll
        for (int kh = 0; kh < 11; kh++) {
            const float* xp = xc + (oh * 4 + kh) * 640 + ow * 4;
            const float* wq = wc + kh * 11;
            #pragma unroll
            for (int kw = 0; kw < 11; kw++) acc = fmaf(xp[kw], wq[kw], acc);
        }
    }
    out[i] = fmaxf(acc, 0.f);
}

// ---- fused stage-1 LRN (size5, a=1e-4, k=2) + maxpool3s2 + upsample (59,79) ----
__global__ void k_pooluplrn(const float* __restrict__ c1, float* __restrict__ out) {
    int i = blockIdx.x * blockDim.x + threadIdx.x;
    if (i >= 96 * 59 * 79) return;
    int c = i / (59 * 79), r = i % (59 * 79), oh = r / 79, ow = r % 79;
    int hi = (oh * 58) / 59, wi = (ow * 78) / 79;
    int jlo = c - 2 > 0 ? c - 2 : 0;
    int jhi = c + 2 < 95 ? c + 2 : 95;
    const int HW = 118 * 158;
    float m = -1e30f;
    #pragma unroll
    for (int dh = 0; dh < 3; dh++) {
        #pragma unroll
        for (int dw = 0; dw < 3; dw++) {
            const float* p = c1 + (2 * hi + dh) * 158 + 2 * wi + dw;
            float s = 0.f;
            for (int j = jlo; j <= jhi; j++) { float v = p[j * HW]; s = fmaf(v, v, s); }
            float t = 2.0f + 1e-4f * s;
            float rr = rsqrtf(t);
            float val = p[c * HW] * rr * sqrtf(rr);   // * t^-0.75
            m = fmaxf(m, val);
        }
    }
    out[i] = m;
}

__global__ void k_lrn(const float* __restrict__ in, float* __restrict__ out,
                      int C, int HW, float kconst, float a) {
    int i = blockIdx.x * blockDim.x + threadIdx.x;
    if (i >= C * HW) return;
    int c = i / HW, s = i % HW;
    int lo = c - 2 > 0 ? c - 2 : 0;
    int hi = c + 2 < C - 1 ? c + 2 : C - 1;
    float sum = 0.f;
    for (int j = lo; j <= hi; j++) { float v = in[j * HW + s]; sum = fmaf(v, v, sum); }
    float t = kconst + a * sum;
    float r = rsqrtf(t);
    out[i] = in[i] * r * sqrtf(r);       // t^-0.75
}

__global__ void k_pool(const float* __restrict__ in, float* __restrict__ out,
                       int C, int Hin, int Win, int Ho, int Wo) {
    int i = blockIdx.x * blockDim.x + threadIdx.x;
    if (i >= C * Ho * Wo) return;
    int c = i / (Ho * Wo), r = i % (Ho * Wo), oh = r / Wo, ow = r % Wo;
    const float* p = in + (c * Hin + 2 * oh) * Win + 2 * ow;
    float m = p[0];
    #pragma unroll
    for (int dh = 0; dh < 3; dh++)
        #pragma unroll
        for (int dw = 0; dw < 3; dw++) m = fmaxf(m, p[dh * Win + dw]);
    out[i] = m;
}

// ---- im2col + transpose + bf16 split, 2D grid ----
__global__ void k_prepB2d(const float* __restrict__ src, __nv_bfloat16* __restrict__ hi,
                          __nv_bfloat16* __restrict__ lo, int H, int W,
                          int ksz, int pad, int Ho, int Wo, int K) {
    int kidx = blockIdx.x * 256 + threadIdx.x;
    if (kidx >= K) return;
    int n = blockIdx.y;
    float v = 0.f;
    if (n < Ho * Wo) {
        int kw = kidx % ksz;
        int t = kidx / ksz;
        int kh = t % ksz, cc = t / ksz;
        int oh = n / Wo, ow = n % Wo;
        int ih = oh - pad + kh, iw = ow - pad + kw;
        if (ih >= 0 && ih < H && iw >= 0 && iw < W) v = src[((size_t)cc * H + ih) * W + iw];
    }
    size_t o = (size_t)n * K + kidx;
    __nv_bfloat16 h = __float2bfloat16(v);
    hi[o] = h;
    lo[o] = __float2bfloat16(v - __bfloat162float(h));
}

// ---- batched split of the four x7 tensors (K=4096, N=300, Npad=320) ----
__global__ void k_prep7b(const float* __restrict__ x7, __nv_bfloat16* __restrict__ hi,
                         __nv_bfloat16* __restrict__ lo) {
    int z = blockIdx.y;
    int i = blockIdx.x * 256 + threadIdx.x;       // 0 .. 320*4096-1
    int n = i >> 12, k = i & 4095;
    float v = 0.f;
    if (n < 300) v = x7[(size_t)z * 1228800 + (size_t)k * 300 + n];
    __nv_bfloat16 h = __float2bfloat16(v);
    size_t o = (size_t)z * 1310720 + i;
    hi[o] = h;
    lo[o] = __float2bfloat16(v - __bfloat162float(h));
}

// ---- fused 4-branch pixel-shuffle tile ----
__global__ void k_tile4(const float* __restrict__ x8, float* __restrict__ out) {
    int i = blockIdx.x * blockDim.x + threadIdx.x;
    if (i >= 518400) return;
    int start, r;
    long oofs;
    if (i < 76800)       { start = 0;      r = 8; oofs = 1228800L; }
    else if (i < 115200) { start = 76800;  r = 8; oofs = 1305600L; }
    else if (i < 422400) { start = 115200; r = 4; oofs = 1344000L; }
    else                 { start = 422400; r = 8; oofs = 1651200L; }
    int li = i - start;
    int OW = 20 * r;
    int OHW = 300 * r * r;
    int oc = li / OHW, rem = li % OHW;
    int oh = rem / OW, ow = rem % OW;
    int ic = oc * r * r + (oh % r) * r + (ow % r);
    out[oofs + li] = x8[start + ic * 300 + (oh / r) * 20 + (ow / r)];
}

// ---- split-K reduce kernels ----
__global__ void k_red6(const float* __restrict__ p, const float* __restrict__ bias,
                       float* __restrict__ out) {
    int i = blockIdx.x * blockDim.x + threadIdx.x;
    if (i >= 4096 * 300) return;
    float v = p[i] + p[i + 1228800] + p[i + 2 * 1228800] + p[i + 3 * 1228800];
    out[i] = fmaxf(v + bias[i / 300], 0.f);
}
struct Bias4 { const float* b[4]; };
__global__ void k_red7(const float* __restrict__ p, Bias4 bias, float* __restrict__ out) {
    int z = blockIdx.y;
    int i = blockIdx.x * blockDim.x + threadIdx.x;
    if (i >= 4096 * 300) return;
    size_t o = (size_t)z * 1228800 + i;
    float v = p[o] + p[o + 4 * 1228800];
    out[o] = fmaxf(v + bias.b[z][i / 300], 0.f);
}
__global__ void k_red8(const float* __restrict__ p, Bias4 bias, float* __restrict__ out) {
    int i = blockIdx.x * blockDim.x + threadIdx.x;
    if (i >= 518400) return;
    float v = p[i] + p[i + 518400] + p[i + 2 * 518400] + p[i + 3 * 518400];
    int row = i / 300;
    float bv;
    if (row < 256)       bv = bias.b[0][row];
    else if (row < 384)  bv = bias.b[1][row - 256];
    else if (row < 1408) bv = bias.b[2][row - 384];
    else                 bv = bias.b[3][row - 1408];
    out[i] = v + bv;
}

// ============================ HMMA GEMM core ============================
// C[M,Ncols] partial/full = A[M,K](fp32, split in-kernel) @ B^T over chunk
// range [c0,cEnd). B pre-split bf16 [Npad][K]. CTA tile 128x64, BK=32,
// 8 warps (4m x 2n), double buffer with ONE barrier per chunk.
#define STG 24576
#define GT_SMEM (2 * STG + 1024)

__device__ __forceinline__ void gemm_core(
    char* dsm, const float* __restrict__ A, const __nv_bfloat16* __restrict__ Bh,
    const __nv_bfloat16* __restrict__ Bl, const float* __restrict__ bias,
    float* __restrict__ C, int M, int K, int Ncols, int relu, int m0, int n0,
    int c0, int cEnd) {
    const int tid = threadIdx.x;
    const int lane = tid & 31;
    const int wid = tid >> 5;
    const int wm = wid & 3, wn = wid >> 2;

    const uint32_t base = (smem_u32(dsm) + 1023u) & ~1023u;
    const int bR = tid >> 2, bF = tid & 3;

    uint32_t pA[2], pB[2];
    {
        uint32_t r = (uint32_t)(wm * 32 + (lane & 15));
        uint32_t kc = (uint32_t)((lane >> 4) * 16);
        #pragma unroll
        for (int mt = 0; mt < 2; mt++) {
            uint32_t o = (r + mt * 16) * 64 + kc;
            pA[mt] = o ^ ((o >> 3) & 0x30);
        }
        uint32_t rn = (uint32_t)(wn * 32 + (lane & 7) + ((lane >> 4) << 3));
        uint32_t kcb = (uint32_t)(((lane >> 3) & 1) * 16);
        #pragma unroll
        for (int nt = 0; nt < 2; nt++) {
            uint32_t o = (rn + nt * 16) * 64 + kcb;
            pB[nt] = o ^ ((o >> 3) & 0x30);
        }
    }

    float acc[2][4][4] = {};

    float4 aP[4];
    uint4 bP[2];
    {
        const int k0 = c0 << 5;
        #pragma unroll
        for (int it = 0; it < 4; it++) {
            int idx = tid + it * 256;
            int row = idx >> 3, f4 = idx & 7;
            int gr = m0 + row;
            aP[it] = (gr < M)
                ? *reinterpret_cast<const float4*>(A + (size_t)gr * K + k0 + f4 * 4)
                : make_float4(0.f, 0.f, 0.f, 0.f);
        }
        bP[0] = *reinterpret_cast<const uint4*>(Bh + (size_t)(n0 + bR) * K + k0 + bF * 8);
        bP[1] = *reinterpret_cast<const uint4*>(Bl + (size_t)(n0 + bR) * K + k0 + bF * 8);
    }

    for (int c = c0; c < cEnd; c++) {
        const uint32_t stg = base + (uint32_t)(c & 1) * STG;
        #pragma unroll
        for (int it = 0; it < 4; it++) {
            int idx = tid + it * 256;
            int row = idx >> 3, f4 = idx & 7;
            float4 v = aP[it];
            __nv_bfloat16 h0 = __float2bfloat16(v.x), h1 = __float2bfloat16(v.y),
                          h2 = __float2bfloat16(v.z), h3 = __float2bfloat16(v.w);
            float l0 = v.x - __bfloat162float(h0), l1 = v.y - __bfloat162float(h1);
            float l2 = v.z - __bfloat162float(h2), l3 = v.w - __bfloat162float(h3);
            uint32_t off = swz64((uint32_t)(row * 64 + f4 * 8));
            sts64(stg + off, packbf2(__bfloat162float(h0), __bfloat162float(h1)),
                             packbf2(__bfloat162float(h2), __bfloat162float(h3)));
            sts64(stg + 8192u + off, packbf2(l0, l1), packbf2(l2, l3));
        }
        {
            uint32_t off = swz64((uint32_t)(bR * 64 + bF * 16));
            sts128(stg + 16384u + off, bP[0]);
            sts128(stg + 20480u + off, bP[1]);
        }
        // ONE barrier per chunk: orders this chunk's stores for all warps AND
        // (transitively) the previous chunk's compute before next overwrite.
        __syncthreads();
        if (c + 1 < cEnd) {
            const int k0 = (c + 1) << 5;
            #pragma unroll
            for (int it = 0; it < 4; it++) {
                int idx = tid + it * 256;
                int row = idx >> 3, f4 = idx & 7;
                int gr = m0 + row;
                aP[it] = (gr < M)
                    ? *reinterpret_cast<const float4*>(A + (size_t)gr * K + k0 + f4 * 4)
                    : make_float4(0.f, 0.f, 0.f, 0.f);
            }
            bP[0] = *reinterpret_cast<const uint4*>(Bh + (size_t)(n0 + bR) * K + k0 + bF * 8);
            bP[1] = *reinterpret_cast<const uint4*>(Bl + (size_t)(n0 + bR) * K + k0 + bF * 8);
        }
        #pragma unroll
        for (int ks = 0; ks < 2; ks++) {
            const uint32_t kb = (uint32_t)(ks << 5);
            uint32_t ah[2][4], al[2][4], bh_[2][4], bl_[2][4];
            ldm4(ah[0], stg + (pA[0] ^ kb));
            ldm4(ah[1], stg + (pA[1] ^ kb));
            ldm4(al[0], stg + 8192u + (pA[0] ^ kb));
            ldm4(al[1], stg + 8192u + (pA[1] ^ kb));
            ldm4(bh_[0], stg + 16384u + (pB[0] ^ kb));
            ldm4(bh_[1], stg + 16384u + (pB[1] ^ kb));
            ldm4(bl_[0], stg + 20480u + (pB[0] ^ kb));
            ldm4(bl_[1], stg + 20480u + (pB[1] ^ kb));
            #pragma unroll
            for (int mt = 0; mt < 2; mt++)
                #pragma unroll
                for (int nt = 0; nt < 4; nt++) {
                    const uint32_t* bh2 = &bh_[nt >> 1][(nt & 1) * 2];
                    const uint32_t* bl2 = &bl_[nt >> 1][(nt & 1) * 2];
                    mma_bf16(acc[mt][nt], ah[mt], bh2);
                    mma_bf16(acc[mt][nt], ah[mt], bl2);
                    mma_bf16(acc[mt][nt], al[mt], bh2);
                }
        }
    }

    #pragma unroll
    for (int mt = 0; mt < 2; mt++) {
        int r0 = m0 + wm * 32 + mt * 16 + (lane >> 2);
        #pragma unroll
        for (int half = 0; half < 2; half++) {
            int row = r0 + half * 8;
            if (row >= M) continue;
            float bv = bias ? bias[row] : 0.f;
            #pragma unroll
            for (int nt = 0; nt < 4; nt++) {
                int col = n0 + wn * 32 + nt * 8 + (lane & 3) * 2;
                float v0 = acc[mt][nt][half * 2 + 0] + bv;
                float v1 = acc[mt][nt][half * 2 + 1] + bv;
                if (relu) { v0 = fmaxf(v0, 0.f); v1 = fmaxf(v1, 0.f); }
                if (col < Ncols) C[(size_t)row * Ncols + col] = v0;
                if (col + 1 < Ncols) C[(size_t)row * Ncols + col + 1] = v1;
            }
        }
    }
}

// full-K GEMM with bias (+optional relu): conv2..5
__global__ __launch_bounds__(256, 2) void k_gemm_tc(
    const float* __restrict__ A, const __nv_bfloat16* __restrict__ Bh,
    const __nv_bfloat16* __restrict__ Bl, const float* __restrict__ bias,
    float* __restrict__ C, int M, int K, int Ncols, int relu) {
    extern __shared__ char dsm[];
    gemm_core(dsm, A, Bh, Bl, bias, C, M, K, Ncols, relu,
              blockIdx.y * 128, blockIdx.x * 64, 0, K >> 5);
}

// conv6 split-K=4
__global__ __launch_bounds__(256, 2) void k_gemm_sk6(
    const float* __restrict__ A, const __nv_bfloat16* __restrict__ Bh,
    const __nv_bfloat16* __restrict__ Bl, float* __restrict__ P) {
    extern __shared__ char dsm[];
    const int z = blockIdx.z;                 // 0..3
    const int per = (13824 >> 5) >> 2;        // 108
    gemm_core(dsm, A, Bh, Bl, nullptr, P + (size_t)z * 1228800,
              4096, 13824, 300, 0, blockIdx.y * 128, blockIdx.x * 64,
              z * per, (z + 1) * per);
}

// gemm7 split-K=2, batched over 4 branches: z = branch*2 + slice
struct Ptr4 { const float* p[4]; };
__global__ __launch_bounds__(256, 2) void k_gemm7(
    Ptr4 W, const __nv_bfloat16* __restrict__ Bh,
    const __nv_bfloat16* __restrict__ Bl, float* __restrict__ P) {
    extern __shared__ char dsm[];
    const int br = blockIdx.z >> 1, sl = blockIdx.z & 1;
    const int per = 128 >> 1;                 // 64 chunks per slice
    float* out = P + (size_t)sl * 4 * 1228800 + (size_t)br * 1228800;
    gemm_core(dsm, W.p[br], Bh, Bl, nullptr, out,
              4096, 4096, 300, 0, blockIdx.y * 128, blockIdx.x * 64,
              sl * per, (sl + 1) * per);
}

// gemm8 split-K=4, batched over 4 branches: z = branch*4 + slice
__global__ __launch_bounds__(256, 2) void k_gemm8(
    Ptr4 W, const __nv_bfloat16* __restrict__ Bh,
    const __nv_bfloat16* __restrict__ Bl, float* __restrict__ P) {
    extern __shared__ char dsm[];
    const int br = blockIdx.z >> 2, sl = blockIdx.z & 3;
    const int C8s[4] = {256, 128, 1024, 320};
    const int roff[4] = {0, 256, 384, 1408};
    const int M = C8s[br];
    const int m0 = blockIdx.y * 128;
    if (m0 >= M) return;
    const int per = 128 >> 2;                 // 32 chunks per slice
    float* out = P + (size_t)sl * 518400 + (size_t)roff[br] * 300;
    gemm_core(dsm, W.p[br], Bh + (size_t)br * 1310720, Bl + (size_t)br * 1310720,
              nullptr, out, M, 4096, 300, 0, m0, blockIdx.x * 64,
              sl * per, (sl + 1) * per);
}

static inline dim3 blk1(long n) { return dim3((unsigned)((n + 255) / 256)); }

extern "C" void kernel_launch(void* const* d_in, const int* in_sizes, int n_in,
                              void* d_out, int out_size) {
    const float* x  = (const float*)d_in[0];
    const float* w1 = (const float*)d_in[1];  const float* b1 = (const float*)d_in[2];
    const float* w2 = (const float*)d_in[3];  const float* b2 = (const float*)d_in[4];
    const float* w3 = (const float*)d_in[5];  const float* b3 = (const float*)d_in[6];
    const float* w4 = (const float*)d_in[7];  const float* b4 = (const float*)d_in[8];
    const float* w5 = (const float*)d_in[9];  const float* b5 = (const float*)d_in[10];
    const float* w6 = (const float*)d_in[11]; const float* b6 = (const float*)d_in[12];
    const float* w7[4] = {(const float*)d_in[13], (const float*)d_in[17],
                          (const float*)d_in[21], (const float*)d_in[25]};
    const float* b7[4] = {(const float*)d_in[14], (const float*)d_in[18],
                          (const float*)d_in[22], (const float*)d_in[26]};
    const float* w8[4] = {(const float*)d_in[15], (const float*)d_in[19],
                          (const float*)d_in[23], (const float*)d_in[27]};
    const float* b8[4] = {(const float*)d_in[16], (const float*)d_in[20],
                          (const float*)d_in[24], (const float*)d_in[28]};
    float* out = (float*)d_out;

    cudaFuncSetAttribute(k_gemm_tc,  cudaFuncAttributeMaxDynamicSharedMemorySize, GT_SMEM);
    cudaFuncSetAttribute(k_gemm_sk6, cudaFuncAttributeMaxDynamicSharedMemorySize, GT_SMEM);
    cudaFuncSetAttribute(k_gemm7,    cudaFuncAttributeMaxDynamicSharedMemorySize, GT_SMEM);
    cudaFuncSetAttribute(k_gemm8,    cudaFuncAttributeMaxDynamicSharedMemorySize, GT_SMEM);

    float *c1, *u1, *c2, *l2, *p2, *c3, *c4, *c5, *p5, *x7, *x8, *p6, *p7, *p8;
    __nv_bfloat16 *bh, *bl, *b6h, *b6l;
    cudaGetSymbolAddress((void**)&c1, g_c1);
    cudaGetSymbolAddress((void**)&u1, g_u1);
    cudaGetSymbolAddress((void**)&c2, g_c2);
    cudaGetSymbolAddress((void**)&l2, g_l2);
    cudaGetSymbolAddress((void**)&p2, g_p2);
    cudaGetSymbolAddress((void**)&c3, g_c3);
    cudaGetSymbolAddress((void**)&c4, g_c4);
    cudaGetSymbolAddress((void**)&c5, g_c5);
    cudaGetSymbolAddress((void**)&p5, g_p5);
    cudaGetSymbolAddress((void**)&x7, g_x7);
    cudaGetSymbolAddress((void**)&x8, g_x8);
    cudaGetSymbolAddress((void**)&p6, g_p6);
    cudaGetSymbolAddress((void**)&p7, g_p7);
    cudaGetSymbolAddress((void**)&p8, g_p8);
    cudaGetSymbolAddress((void**)&bh, gB_hi);
    cudaGetSymbolAddress((void**)&bl, gB_lo);
    cudaGetSymbolAddress((void**)&b6h, gB6_hi);
    cudaGetSymbolAddress((void**)&b6l, gB6_lo);

    // stage 1: conv1 -> fused LRN+pool+upsample
    k_conv1<<<blk1(96L * 118 * 158), 256>>>(x, w1, b1, c1);                 // launch 0
    k_pooluplrn<<<blk1(96L * 59 * 79), 256>>>(c1, u1);                      // launch 1

    // conv2: M=256 K=2400 N=4661 (Npad 4672)
    k_prepB2d<<<dim3(10, 4672), 256>>>(u1, bh, bl, 59, 79, 5, 2, 59, 79, 2400);     // 2
    k_gemm_tc<<<dim3(73, 2), 256, GT_SMEM>>>(w2, bh, bl, b2, c2, 256, 2400, 4661, 1); // 3 <- ncu
    k_lrn<<<blk1(256L * 4661), 256>>>(c2, l2, 256, 4661, 8.0f, 0.0001f);
    k_pool<<<blk1(256L * 29 * 39), 256>>>(l2, p2, 256, 59, 79, 29, 39);

    // conv3: M=384 K=2304 N=1131 (Npad 1152)
    k_prepB2d<<<dim3(9, 1152), 256>>>(p2, bh, bl, 29, 39, 3, 1, 29, 39, 2304);
    k_gemm_tc<<<dim3(18, 3), 256, GT_SMEM>>>(w3, bh, bl, b3, c3, 384, 2304, 1131, 1);
    // conv4: K=3456
    k_prepB2d<<<dim3(14, 1152), 256>>>(c3, bh, bl, 29, 39, 3, 1, 29, 39, 3456);
    k_gemm_tc<<<dim3(18, 3), 256, GT_SMEM>>>(w4, bh, bl, b4, c4, 384, 3456, 1131, 1);
    // conv5
    k_prepB2d<<<dim3(14, 1152), 256>>>(c4, bh, bl, 29, 39, 3, 1, 29, 39, 3456);
    k_gemm_tc<<<dim3(18, 3), 256, GT_SMEM>>>(w5, bh, bl, b5, c5, 384, 3456, 1131, 1);
    k_pool<<<blk1(384L * 14 * 19), 256>>>(c5, p5, 384, 29, 39, 14, 19);

    // conv6: M=4096 K=13824 N=300 (Npad 320), split-K=4 -> reduce into d_out
    k_prepB2d<<<dim3(54, 320), 256>>>(p5, bh, bl, 14, 19, 6, 3, 15, 20, 13824);
    k_gemm_sk6<<<dim3(5, 32, 4), 256, GT_SMEM>>>(w6, bh, bl, p6);
    k_red6<<<blk1(4096L * 300), 256>>>(p6, b6, out);

    // split x6 once (1x1 conv layout)
    k_prepB2d<<<dim3(16, 320), 256>>>(out, b6h, b6l, 15, 20, 1, 0, 15, 20, 4096);

    // gemm7: all 4 branches, split-K=2 -> partials -> reduce into x7
    Ptr4 W7 = {{w7[0], w7[1], w7[2], w7[3]}};
    k_gemm7<<<dim3(5, 32, 8), 256, GT_SMEM>>>(W7, b6h, b6l, p7);
    Bias4 B7 = {{b7[0], b7[1], b7[2], b7[3]}};
    k_red7<<<dim3((unsigned)((1228800 + 255) / 256), 4), 256>>>(p7, B7, x7);

    // split all four x7 tensors
    k_prep7b<<<dim3(5120, 4), 256>>>(x7, bh, bl);

    // gemm8: all 4 branches packed [256|128|1024|320], split-K=4 -> reduce
    Ptr4 W8 = {{w8[0], w8[1], w8[2], w8[3]}};
    k_gemm8<<<dim3(5, 8, 16), 256, GT_SMEM>>>(W8, bh, bl, p8);
    Bias4 B8 = {{b8[0], b8[1], b8[2], b8[3]}};
    k_red8<<<blk1(518400L), 256>>>(p8, B8, x8);

    // fused pixel-shuffle for all branches
    k_tile4<<<blk1(518400L), 256>>>(x8, out);
}

// round 7
// speedup vs baseline: 2.0261x; 1.1677x over previous
#include <cuda_runtime.h>
#include <cuda_bf16.h>
#include <math.h>
#include <stdint.h>

// ---------------------------------------------------------------------------
// VPGNet forward. Conv GEMMs via warp-level mma.sync bf16 (2-term split,
// fp32 accumulate). Split-K everywhere so every GEMM launch >= ~292 CTAs
// (2 CTAs/SM co-residency). Output: [x6|x8a|x8b|x8c|x8d] = 1,747,200 floats
// ---------------------------------------------------------------------------

// ---- scratch (__device__ globals: no allocation allowed) ----
__device__ float g_c1[96 * 118 * 158];
__device__ float g_u1[96 * 59 * 79];
__device__ float g_c2[256 * 59 * 79];
__device__ float g_p2[256 * 29 * 39];
__device__ float g_c3[384 * 29 * 39];
__device__ float g_c4[384 * 29 * 39];
__device__ float g_c5[384 * 29 * 39];
__device__ float g_p5[384 * 14 * 19];
__device__ float g_x7[4 * 4096 * 300];
__device__ float g_x8[1728 * 300];
// split-K partial buffers (g_p6 also reused for conv2..5 partials)
__device__ float g_p6[4 * 4096 * 300];        // 4.9M floats
__device__ float g_p7[2 * 4 * 4096 * 300];
__device__ float g_p8[4 * 1728 * 300];
// bf16 split activation buffers [Npad][K]; max conv2: 4672*2400
__device__ __nv_bfloat16 gB_hi[11250000];
__device__ __nv_bfloat16 gB_lo[11250000];
__device__ __nv_bfloat16 gB6_hi[320 * 4096];
__device__ __nv_bfloat16 gB6_lo[320 * 4096];

// ============================ helpers ============================
__device__ __forceinline__ uint32_t smem_u32(const void* p) {
    uint32_t a;
    asm("{ .reg .u64 t; cvta.to.shared.u64 t, %1; cvt.u32.u64 %0, t; }" : "=r"(a) : "l"(p));
    return a;
}
__device__ __forceinline__ uint32_t swz64(uint32_t o) { return o ^ ((o >> 3) & 0x30); }

__device__ __forceinline__ void ldm4(uint32_t* r, uint32_t a) {
    asm volatile("ldmatrix.sync.aligned.m8n8.x4.shared.b16 {%0,%1,%2,%3}, [%4];"
                 : "=r"(r[0]), "=r"(r[1]), "=r"(r[2]), "=r"(r[3]) : "r"(a));
}
__device__ __forceinline__ void mma_bf16(float* c, const uint32_t* a, const uint32_t* b) {
    asm volatile("mma.sync.aligned.m16n8k16.row.col.f32.bf16.bf16.f32 "
                 "{%0,%1,%2,%3}, {%4,%5,%6,%7}, {%8,%9}, {%0,%1,%2,%3};"
                 : "+f"(c[0]), "+f"(c[1]), "+f"(c[2]), "+f"(c[3])
                 : "r"(a[0]), "r"(a[1]), "r"(a[2]), "r"(a[3]), "r"(b[0]), "r"(b[1]));
}
__device__ __forceinline__ void sts128(uint32_t a, uint4 v) {
    asm volatile("st.shared.v4.b32 [%0], {%1,%2,%3,%4};"
                 :: "r"(a), "r"(v.x), "r"(v.y), "r"(v.z), "r"(v.w) : "memory");
}
__device__ __forceinline__ void sts64(uint32_t a, uint32_t x, uint32_t y) {
    asm volatile("st.shared.v2.b32 [%0], {%1,%2};" :: "r"(a), "r"(x), "r"(y) : "memory");
}
__device__ __forceinline__ uint32_t packbf2(float lo, float hi) {
    uint32_t d;
    asm("cvt.rn.bf16x2.f32 %0, %1, %2;" : "=r"(d) : "f"(hi), "f"(lo));
    return d;
}

// ============================ small layers ============================
__global__ void k_conv1(const float* __restrict__ x, const float* __restrict__ w,
                        const float* __restrict__ b, float* __restrict__ out) {
    const int HO = 118, WO = 158;
    int i = blockIdx.x * blockDim.x + threadIdx.x;
    if (i >= 96 * HO * WO) return;
    int c = i / (HO * WO), r = i % (HO * WO), oh = r / WO, ow = r % WO;
    float acc = b[c];
    const float* wp = w + c * 3 * 121;
    for (int ci = 0; ci < 3; ci++) {
        const float* xc = x + ci * 480 * 640;
        const float* wc = wp + ci * 121;
        #pragma unroll
        for (int kh = 0; kh < 11; kh++) {
            const float* xp = xc + (oh * 4 + kh) * 640 + ow * 4;
            const float* wq = wc + kh * 11;
            #pragma unroll
            for (int kw = 0; kw < 11; kw++) acc = fmaf(xp[kw], wq[kw], acc);
        }
    }
    out[i] = fmaxf(acc, 0.f);
}

// ---- fused stage-1 LRN + maxpool3s2 + upsample (59,79) ----
__global__ void k_pooluplrn(const float* __restrict__ c1, float* __restrict__ out) {
    int i = blockIdx.x * blockDim.x + threadIdx.x;
    if (i >= 96 * 59 * 79) return;
    int c = i / (59 * 79), r = i % (59 * 79), oh = r / 79, ow = r % 79;
    int hi = (oh * 58) / 59, wi = (ow * 78) / 79;
    int jlo = c - 2 > 0 ? c - 2 : 0;
    int jhi = c + 2 < 95 ? c + 2 : 95;
    const int HW = 118 * 158;
    float m = -1e30f;
    #pragma unroll
    for (int dh = 0; dh < 3; dh++) {
        #pragma unroll
        for (int dw = 0; dw < 3; dw++) {
            const float* p = c1 + (2 * hi + dh) * 158 + 2 * wi + dw;
            float s = 0.f;
            for (int j = jlo; j <= jhi; j++) { float v = p[j * HW]; s = fmaf(v, v, s); }
            float t = 2.0f + 1e-4f * s;
            float rr = rsqrtf(t);
            m = fmaxf(m, p[c * HW] * rr * sqrtf(rr));
        }
    }
    out[i] = m;
}

// ---- fused conv2 LRN (k=8, a=1e-4) + maxpool3s2 ----
__global__ void k_poollrn(const float* __restrict__ in, float* __restrict__ out,
                          int C, int Hin, int Win, int Ho, int Wo,
                          float kc, float a) {
    int i = blockIdx.x * blockDim.x + threadIdx.x;
    if (i >= C * Ho * Wo) return;
    int c = i / (Ho * Wo), r = i % (Ho * Wo), oh = r / Wo, ow = r % Wo;
    int jlo = c - 2 > 0 ? c - 2 : 0;
    int jhi = c + 2 < C - 1 ? c + 2 : C - 1;
    const int HW = Hin * Win;
    float m = -1e30f;
    #pragma unroll
    for (int dh = 0; dh < 3; dh++) {
        #pragma unroll
        for (int dw = 0; dw < 3; dw++) {
            const float* p = in + (2 * oh + dh) * Win + 2 * ow + dw;
            float s = 0.f;
            for (int j = jlo; j <= jhi; j++) { float v = p[j * HW]; s = fmaf(v, v, s); }
            float t = kc + a * s;
            float rr = rsqrtf(t);
            m = fmaxf(m, p[c * HW] * rr * sqrtf(rr));
        }
    }
    out[i] = m;
}

__global__ void k_pool(const float* __restrict__ in, float* __restrict__ out,
                       int C, int Hin, int Win, int Ho, int Wo) {
    int i = blockIdx.x * blockDim.x + threadIdx.x;
    if (i >= C * Ho * Wo) return;
    int c = i / (Ho * Wo), r = i % (Ho * Wo), oh = r / Wo, ow = r % Wo;
    const float* p = in + (c * Hin + 2 * oh) * Win + 2 * ow;
    float m = p[0];
    #pragma unroll
    for (int dh = 0; dh < 3; dh++)
        #pragma unroll
        for (int dw = 0; dw < 3; dw++) m = fmaxf(m, p[dh * Win + dw]);
    out[i] = m;
}

// ---- im2col + transpose + bf16 split, 2D grid, ksz compile-time ----
template <int KSZ>
__global__ void k_prepB2d(const float* __restrict__ src, __nv_bfloat16* __restrict__ hi,
                          __nv_bfloat16* __restrict__ lo, int H, int W,
                          int pad, int Ho, int Wo, int K) {
    int kidx = blockIdx.x * 256 + threadIdx.x;
    if (kidx >= K) return;
    int n = blockIdx.y;
    float v = 0.f;
    if (n < Ho * Wo) {
        int kw = kidx % KSZ;
        int t = kidx / KSZ;
        int kh = t % KSZ, cc = t / KSZ;
        int oh = n / Wo, ow = n % Wo;
        int ih = oh - pad + kh, iw = ow - pad + kw;
        if (ih >= 0 && ih < H && iw >= 0 && iw < W) v = src[((size_t)cc * H + ih) * W + iw];
    }
    size_t o = (size_t)n * K + kidx;
    __nv_bfloat16 h = __float2bfloat16(v);
    hi[o] = h;
    lo[o] = __float2bfloat16(v - __bfloat162float(h));
}

// ---- batched split of the four x7 tensors ----
__global__ void k_prep7b(const float* __restrict__ x7, __nv_bfloat16* __restrict__ hi,
                         __nv_bfloat16* __restrict__ lo) {
    int z = blockIdx.y;
    int i = blockIdx.x * 256 + threadIdx.x;
    int n = i >> 12, k = i & 4095;
    float v = 0.f;
    if (n < 300) v = x7[(size_t)z * 1228800 + (size_t)k * 300 + n];
    __nv_bfloat16 h = __float2bfloat16(v);
    size_t o = (size_t)z * 1310720 + i;
    hi[o] = h;
    lo[o] = __float2bfloat16(v - __bfloat162float(h));
}

// ---- fused 4-branch pixel-shuffle tile ----
__global__ void k_tile4(const float* __restrict__ x8, float* __restrict__ out) {
    int i = blockIdx.x * blockDim.x + threadIdx.x;
    if (i >= 518400) return;
    int start, r;
    long oofs;
    if (i < 76800)       { start = 0;      r = 8; oofs = 1228800L; }
    else if (i < 115200) { start = 76800;  r = 8; oofs = 1305600L; }
    else if (i < 422400) { start = 115200; r = 4; oofs = 1344000L; }
    else                 { start = 422400; r = 8; oofs = 1651200L; }
    int li = i - start;
    int OW = 20 * r;
    int OHW = 300 * r * r;
    int oc = li / OHW, rem = li % OHW;
    int oh = rem / OW, ow = rem % OW;
    int ic = oc * r * r + (oh % r) * r + (ow % r);
    out[oofs + li] = x8[start + ic * 300 + (oh / r) * 20 + (ow / r)];
}

// ---- split-K reduce kernels ----
// generic: out[i] = act( sum_s p[s*stride+i] + bias[i/Ncols] )
__global__ void k_redG(const float* __restrict__ p, const float* __restrict__ bias,
                       float* __restrict__ out, int total, int Ncols, int S,
                       long stride, int relu) {
    int i = blockIdx.x * blockDim.x + threadIdx.x;
    if (i >= total) return;
    float v = 0.f;
    for (int s = 0; s < S; s++) v += p[(size_t)s * stride + i];
    v += bias[i / Ncols];
    out[i] = relu ? fmaxf(v, 0.f) : v;
}
__global__ void k_red6(const float* __restrict__ p, const float* __restrict__ bias,
                       float* __restrict__ out) {
    int i = blockIdx.x * blockDim.x + threadIdx.x;
    if (i >= 4096 * 300) return;
    float v = p[i] + p[i + 1228800] + p[i + 2 * 1228800] + p[i + 3 * 1228800];
    out[i] = fmaxf(v + bias[i / 300], 0.f);
}
struct Bias4 { const float* b[4]; };
__global__ void k_red7(const float* __restrict__ p, Bias4 bias, float* __restrict__ out) {
    int z = blockIdx.y;
    int i = blockIdx.x * blockDim.x + threadIdx.x;
    if (i >= 4096 * 300) return;
    size_t o = (size_t)z * 1228800 + i;
    float v = p[o] + p[o + 4 * 1228800];
    out[o] = fmaxf(v + bias.b[z][i / 300], 0.f);
}
__global__ void k_red8(const float* __restrict__ p, Bias4 bias, float* __restrict__ out) {
    int i = blockIdx.x * blockDim.x + threadIdx.x;
    if (i >= 518400) return;
    float v = p[i] + p[i + 518400] + p[i + 2 * 518400] + p[i + 3 * 518400];
    int row = i / 300;
    float bv;
    if (row < 256)       bv = bias.b[0][row];
    else if (row < 384)  bv = bias.b[1][row - 256];
    else if (row < 1408) bv = bias.b[2][row - 384];
    else                 bv = bias.b[3][row - 1408];
    out[i] = v + bv;
}

// ============================ HMMA GEMM core ============================
#define STG 24576
#define GT_SMEM (2 * STG + 1024)

__device__ __forceinline__ void gemm_core(
    char* dsm, const float* __restrict__ A, const __nv_bfloat16* __restrict__ Bh,
    const __nv_bfloat16* __restrict__ Bl, const float* __restrict__ bias,
    float* __restrict__ C, int M, int K, int Ncols, int relu, int m0, int n0,
    int c0, int cEnd) {
    const int tid = threadIdx.x;
    const int lane = tid & 31;
    const int wid = tid >> 5;
    const int wm = wid & 3, wn = wid >> 2;

    const uint32_t base = (smem_u32(dsm) + 1023u) & ~1023u;
    const int bR = tid >> 2, bF = tid & 3;

    uint32_t pA[2], pB[2];
    {
        uint32_t r = (uint32_t)(wm * 32 + (lane & 15));
        uint32_t kc = (uint32_t)((lane >> 4) * 16);
        #pragma unroll
        for (int mt = 0; mt < 2; mt++) {
            uint32_t o = (r + mt * 16) * 64 + kc;
            pA[mt] = o ^ ((o >> 3) & 0x30);
        }
        uint32_t rn = (uint32_t)(wn * 32 + (lane & 7) + ((lane >> 4) << 3));
        uint32_t kcb = (uint32_t)(((lane >> 3) & 1) * 16);
        #pragma unroll
        for (int nt = 0; nt < 2; nt++) {
            uint32_t o = (rn + nt * 16) * 64 + kcb;
            pB[nt] = o ^ ((o >> 3) & 0x30);
        }
    }

    float acc[2][4][4] = {};

    float4 aP[4];
    uint4 bP[2];
    {
        const int k0 = c0 << 5;
        #pragma unroll
        for (int it = 0; it < 4; it++) {
            int idx = tid + it * 256;
            int row = idx >> 3, f4 = idx & 7;
            int gr = m0 + row;
            aP[it] = (gr < M)
                ? *reinterpret_cast<const float4*>(A + (size_t)gr * K + k0 + f4 * 4)
                : make_float4(0.f, 0.f, 0.f, 0.f);
        }
        bP[0] = *reinterpret_cast<const uint4*>(Bh + (size_t)(n0 + bR) * K + k0 + bF * 8);
        bP[1] = *reinterpret_cast<const uint4*>(Bl + (size_t)(n0 + bR) * K + k0 + bF * 8);
    }

    for (int c = c0; c < cEnd; c++) {
        const uint32_t stg = base + (uint32_t)(c & 1) * STG;
        #pragma unroll
        for (int it = 0; it < 4; it++) {
            int idx = tid + it * 256;
            int row = idx >> 3, f4 = idx & 7;
            float4 v = aP[it];
            __nv_bfloat16 h0 = __float2bfloat16(v.x), h1 = __float2bfloat16(v.y),
                          h2 = __float2bfloat16(v.z), h3 = __float2bfloat16(v.w);
            float l0 = v.x - __bfloat162float(h0), l1 = v.y - __bfloat162float(h1);
            float l2 = v.z - __bfloat162float(h2), l3 = v.w - __bfloat162float(h3);
            uint32_t off = swz64((uint32_t)(row * 64 + f4 * 8));
            sts64(stg + off, packbf2(__bfloat162float(h0), __bfloat162float(h1)),
                             packbf2(__bfloat162float(h2), __bfloat162float(h3)));
            sts64(stg + 8192u + off, packbf2(l0, l1), packbf2(l2, l3));
        }
        {
            uint32_t off = swz64((uint32_t)(bR * 64 + bF * 16));
            sts128(stg + 16384u + off, bP[0]);
            sts128(stg + 20480u + off, bP[1]);
        }
        __syncthreads();   // one barrier per chunk (ping-pong makes it sufficient)
        if (c + 1 < cEnd) {
            const int k0 = (c + 1) << 5;
            #pragma unroll
            for (int it = 0; it < 4; it++) {
                int idx = tid + it * 256;
                int row = idx >> 3, f4 = idx & 7;
                int gr = m0 + row;
                aP[it] = (gr < M)
                    ? *reinterpret_cast<const float4*>(A + (size_t)gr * K + k0 + f4 * 4)
                    : make_float4(0.f, 0.f, 0.f, 0.f);
            }
            bP[0] = *reinterpret_cast<const uint4*>(Bh + (size_t)(n0 + bR) * K + k0 + bF * 8);
            bP[1] = *reinterpret_cast<const uint4*>(Bl + (size_t)(n0 + bR) * K + k0 + bF * 8);
        }
        #pragma unroll
        for (int ks = 0; ks < 2; ks++) {
            const uint32_t kb = (uint32_t)(ks << 5);
            uint32_t ah[2][4], al[2][4], bh_[2][4], bl_[2][4];
            ldm4(ah[0], stg + (pA[0] ^ kb));
            ldm4(ah[1], stg + (pA[1] ^ kb));
            ldm4(al[0], stg + 8192u + (pA[0] ^ kb));
            ldm4(al[1], stg + 8192u + (pA[1] ^ kb));
            ldm4(bh_[0], stg + 16384u + (pB[0] ^ kb));
            ldm4(bh_[1], stg + 16384u + (pB[1] ^ kb));
            ldm4(bl_[0], stg + 20480u + (pB[0] ^ kb));
            ldm4(bl_[1], stg + 20480u + (pB[1] ^ kb));
            #pragma unroll
            for (int mt = 0; mt < 2; mt++)
                #pragma unroll
                for (int nt = 0; nt < 4; nt++) {
                    const uint32_t* bh2 = &bh_[nt >> 1][(nt & 1) * 2];
                    const uint32_t* bl2 = &bl_[nt >> 1][(nt & 1) * 2];
                    mma_bf16(acc[mt][nt], ah[mt], bh2);
                    mma_bf16(acc[mt][nt], ah[mt], bl2);
                    mma_bf16(acc[mt][nt], al[mt], bh2);
                }
        }
    }

    #pragma unroll
    for (int mt = 0; mt < 2; mt++) {
        int r0 = m0 + wm * 32 + mt * 16 + (lane >> 2);
        #pragma unroll
        for (int half = 0; half < 2; half++) {
            int row = r0 + half * 8;
            if (row >= M) continue;
            float bv = bias ? bias[row] : 0.f;
            #pragma unroll
            for (int nt = 0; nt < 4; nt++) {
                int col = n0 + wn * 32 + nt * 8 + (lane & 3) * 2;
                float v0 = acc[mt][nt][half * 2 + 0] + bv;
                float v1 = acc[mt][nt][half * 2 + 1] + bv;
                if (relu) { v0 = fmaxf(v0, 0.f); v1 = fmaxf(v1, 0.f); }
                if (col < Ncols) C[(size_t)row * Ncols + col] = v0;
                if (col + 1 < Ncols) C[(size_t)row * Ncols + col + 1] = v1;
            }
        }
    }
}

// generic split-K GEMM -> raw partials P[z*stride ...]
__global__ __launch_bounds__(256, 2) void k_gemm_skG(
    const float* __restrict__ A, const __nv_bfloat16* __restrict__ Bh,
    const __nv_bfloat16* __restrict__ Bl, float* __restrict__ P,
    int M, int K, int Ncols, int S, long stride) {
    extern __shared__ char dsm[];
    const int z = blockIdx.z;
    const int nc = K >> 5;
    const int per = nc / S, rem = nc % S;
    const int c0 = z * per + (z < rem ? z : rem);
    const int cEnd = c0 + per + (z < rem ? 1 : 0);
    gemm_core(dsm, A, Bh, Bl, nullptr, P + (size_t)z * stride,
              M, K, Ncols, 0, blockIdx.y * 128, blockIdx.x * 64, c0, cEnd);
}

// conv6 split-K=4
__global__ __launch_bounds__(256, 2) void k_gemm_sk6(
    const float* __restrict__ A, const __nv_bfloat16* __restrict__ Bh,
    const __nv_bfloat16* __restrict__ Bl, float* __restrict__ P) {
    extern __shared__ char dsm[];
    const int z = blockIdx.z;
    const int per = (13824 >> 5) >> 2;        // 108
    gemm_core(dsm, A, Bh, Bl, nullptr, P + (size_t)z * 1228800,
              4096, 13824, 300, 0, blockIdx.y * 128, blockIdx.x * 64,
              z * per, (z + 1) * per);
}

struct Ptr4 { const float* p[4]; };
__global__ __launch_bounds__(256, 2) void k_gemm7(
    Ptr4 W, const __nv_bfloat16* __restrict__ Bh,
    const __nv_bfloat16* __restrict__ Bl, float* __restrict__ P) {
    extern __shared__ char dsm[];
    const int br = blockIdx.z >> 1, sl = blockIdx.z & 1;
    const int per = 128 >> 1;
    float* out = P + (size_t)sl * 4 * 1228800 + (size_t)br * 1228800;
    gemm_core(dsm, W.p[br], Bh, Bl, nullptr, out,
              4096, 4096, 300, 0, blockIdx.y * 128, blockIdx.x * 64,
              sl * per, (sl + 1) * per);
}

__global__ __launch_bounds__(256, 2) void k_gemm8(
    Ptr4 W, const __nv_bfloat16* __restrict__ Bh,
    const __nv_bfloat16* __restrict__ Bl, float* __restrict__ P) {
    extern __shared__ char dsm[];
    const int br = blockIdx.z >> 2, sl = blockIdx.z & 3;
    const int C8s[4] = {256, 128, 1024, 320};
    const int roff[4] = {0, 256, 384, 1408};
    const int M = C8s[br];
    const int m0 = blockIdx.y * 128;
    if (m0 >= M) return;
    const int per = 128 >> 2;
    float* out = P + (size_t)sl * 518400 + (size_t)roff[br] * 300;
    gemm_core(dsm, W.p[br], Bh + (size_t)br * 1310720, Bl + (size_t)br * 1310720,
              nullptr, out, M, 4096, 300, 0, m0, blockIdx.x * 64,
              sl * per, (sl + 1) * per);
}

static inline dim3 blk1(long n) { return dim3((unsigned)((n + 255) / 256)); }

extern "C" void kernel_launch(void* const* d_in, const int* in_sizes, int n_in,
                              void* d_out, int out_size) {
    const float* x  = (const float*)d_in[0];
    const float* w1 = (const float*)d_in[1];  const float* b1 = (const float*)d_in[2];
    const float* w2 = (const float*)d_in[3];  const float* b2 = (const float*)d_in[4];
    const float* w3 = (const float*)d_in[5];  const float* b3 = (const float*)d_in[6];
    const float* w4 = (const float*)d_in[7];  const float* b4 = (const float*)d_in[8];
    const float* w5 = (const float*)d_in[9];  const float* b5 = (const float*)d_in[10];
    const float* w6 = (const float*)d_in[11]; const float* b6 = (const float*)d_in[12];
    const float* w7[4] = {(const float*)d_in[13], (const float*)d_in[17],
                          (const float*)d_in[21], (const float*)d_in[25]};
    const float* b7[4] = {(const float*)d_in[14], (const float*)d_in[18],
                          (const float*)d_in[22], (const float*)d_in[26]};
    const float* w8[4] = {(const float*)d_in[15], (const float*)d_in[19],
                          (const float*)d_in[23], (const float*)d_in[27]};
    const float* b8[4] = {(const float*)d_in[16], (const float*)d_in[20],
                          (const float*)d_in[24], (const float*)d_in[28]};
    float* out = (float*)d_out;

    cudaFuncSetAttribute(k_gemm_skG, cudaFuncAttributeMaxDynamicSharedMemorySize, GT_SMEM);
    cudaFuncSetAttribute(k_gemm_sk6, cudaFuncAttributeMaxDynamicSharedMemorySize, GT_SMEM);
    cudaFuncSetAttribute(k_gemm7,    cudaFuncAttributeMaxDynamicSharedMemorySize, GT_SMEM);
    cudaFuncSetAttribute(k_gemm8,    cudaFuncAttributeMaxDynamicSharedMemorySize, GT_SMEM);

    float *c1, *u1, *c2, *p2, *c3, *c4, *c5, *p5, *x7, *x8, *p6, *p7, *p8;
    __nv_bfloat16 *bh, *bl, *b6h, *b6l;
    cudaGetSymbolAddress((void**)&c1, g_c1);
    cudaGetSymbolAddress((void**)&u1, g_u1);
    cudaGetSymbolAddress((void**)&c2, g_c2);
    cudaGetSymbolAddress((void**)&p2, g_p2);
    cudaGetSymbolAddress((void**)&c3, g_c3);
    cudaGetSymbolAddress((void**)&c4, g_c4);
    cudaGetSymbolAddress((void**)&c5, g_c5);
    cudaGetSymbolAddress((void**)&p5, g_p5);
    cudaGetSymbolAddress((void**)&x7, g_x7);
    cudaGetSymbolAddress((void**)&x8, g_x8);
    cudaGetSymbolAddress((void**)&p6, g_p6);
    cudaGetSymbolAddress((void**)&p7, g_p7);
    cudaGetSymbolAddress((void**)&p8, g_p8);
    cudaGetSymbolAddress((void**)&bh, gB_hi);
    cudaGetSymbolAddress((void**)&bl, gB_lo);
    cudaGetSymbolAddress((void**)&b6h, gB6_hi);
    cudaGetSymbolAddress((void**)&b6l, gB6_lo);

    // stage 1: conv1 -> fused LRN+pool+upsample
    k_conv1<<<blk1(96L * 118 * 158), 256>>>(x, w1, b1, c1);
    k_pooluplrn<<<blk1(96L * 59 * 79), 256>>>(c1, u1);

    // conv2: M=256 K=2400 N=4661 (Npad 4672), split-K=2 (75 chunks -> 38+37)
    k_prepB2d<5><<<dim3(10, 4672), 256>>>(u1, bh, bl, 59, 79, 2, 59, 79, 2400);
    k_gemm_skG<<<dim3(73, 2, 2), 256, GT_SMEM>>>(w2, bh, bl, p6,
                                                 256, 2400, 4661, 2, 1193216L);
    k_redG<<<blk1(1193216L), 256>>>(p6, b2, c2, 1193216, 4661, 2, 1193216L, 1);
    // fused LRN(k=8) + pool -> p2
    k_poollrn<<<blk1(256L * 29 * 39), 256>>>(c2, p2, 256, 59, 79, 29, 39, 8.0f, 1e-4f);

    // conv3: M=384 K=2304 N=1131 (Npad 1152), split-K=4 (72 -> 18 each)
    k_prepB2d<3><<<dim3(9, 1152), 256>>>(p2, bh, bl, 29, 39, 1, 29, 39, 2304);
    k_gemm_skG<<<dim3(18, 3, 4), 256, GT_SMEM>>>(w3, bh, bl, p6,
                                                 384, 2304, 1131, 4, 434304L);
    k_redG<<<blk1(434304L), 256>>>(p6, b3, c3, 434304, 1131, 4, 434304L, 1);
    // conv4: K=3456, split-K=4 (108 -> 27 each)
    k_prepB2d<3><<<dim3(14, 1152), 256>>>(c3, bh, bl, 29, 39, 1, 29, 39, 3456);
    k_gemm_skG<<<dim3(18, 3, 4), 256, GT_SMEM>>>(w4, bh, bl, p6,
                                                 384, 3456, 1131, 4, 434304L);
    k_redG<<<blk1(434304L), 256>>>(p6, b4, c4, 434304, 1131, 4, 434304L, 1);
    // conv5
    k_prepB2d<3><<<dim3(14, 1152), 256>>>(c4, bh, bl, 29, 39, 1, 29, 39, 3456);
    k_gemm_skG<<<dim3(18, 3, 4), 256, GT_SMEM>>>(w5, bh, bl, p6,
                                                 384, 3456, 1131, 4, 434304L);
    k_redG<<<blk1(434304L), 256>>>(p6, b5, c5, 434304, 1131, 4, 434304L, 1);
    k_pool<<<blk1(384L * 14 * 19), 256>>>(c5, p5, 384, 29, 39, 14, 19);

    // conv6: M=4096 K=13824 N=300 (Npad 320), split-K=4 -> reduce into d_out
    k_prepB2d<6><<<dim3(54, 320), 256>>>(p5, bh, bl, 14, 19, 3, 15, 20, 13824);
    k_gemm_sk6<<<dim3(5, 32, 4), 256, GT_SMEM>>>(w6, bh, bl, p6);
    k_red6<<<blk1(4096L * 300), 256>>>(p6, b6, out);

    // split x6 once (1x1 conv layout)
    k_prepB2d<1><<<dim3(16, 320), 256>>>(out, b6h, b6l, 15, 20, 0, 15, 20, 4096);

    // gemm7: all 4 branches, split-K=2 -> partials -> reduce into x7
    Ptr4 W7 = {{w7[0], w7[1], w7[2], w7[3]}};
    k_gemm7<<<dim3(5, 32, 8), 256, GT_SMEM>>>(W7, b6h, b6l, p7);
    Bias4 B7 = {{b7[0], b7[1], b7[2], b7[3]}};
    k_red7<<<dim3((unsigned)((1228800 + 255) / 256), 4), 256>>>(p7, B7, x7);

    // split all four x7 tensors
    k_prep7b<<<dim3(5120, 4), 256>>>(x7, bh, bl);

    // gemm8: all 4 branches packed [256|128|1024|320], split-K=4 -> reduce
    Ptr4 W8 = {{w8[0], w8[1], w8[2], w8[3]}};
    k_gemm8<<<dim3(5, 8, 16), 256, GT_SMEM>>>(W8, bh, bl, p8);
    Bias4 B8 = {{b8[0], b8[1], b8[2], b8[3]}};
    k_red8<<<blk1(518400L), 256>>>(p8, B8, x8);

    // fused pixel-shuffle for all branches
    k_tile4<<<blk1(518400L), 256>>>(x8, out);
}